// round 10
// baseline (speedup 1.0000x reference)
#include <cuda_runtime.h>
#include <cuda_fp16.h>

#define N_NODES 50000
#define N_EDGES 800000
#define N_FEAT  512
#define N_HID   256
#define N_LAYER 4
#define N_CLASS 40
#define JK_DIM  (N_HID * N_LAYER)   // 1024

// ---------------- scratch (device globals; no allocation allowed) ----------
__device__ int   g_cnt[N_NODES];
__device__ int   g_off[N_NODES + 1];
__device__ int   g_cur[N_NODES];
__device__ int   g_bsum[16];
__device__ int   g_boff[16];
__device__ __align__(16) int2 g_edge[N_EDGES];      // {src, coef bits}
__device__ float g_dinv[N_NODES];
__device__ float g_selfn[N_NODES];
// GEMM outputs stored fp16 (gather traffic halved); aggregation math is fp32
__device__ __align__(256) __half g_hw [N_NODES * N_HID];           // 25.6 MB
__device__ __align__(256) __half g_lin[N_NODES * N_HID];           // 25.6 MB
// fp16 hi/lo activation slabs (A-side operands, exact to 2^-22)
__device__ __align__(256) __half g_jkh[(size_t)N_NODES * JK_DIM];
__device__ __align__(256) __half g_jkl[(size_t)N_NODES * JK_DIM];
__device__ __align__(256) __half g_xh[(size_t)N_NODES * N_FEAT];
__device__ __align__(256) __half g_xl[(size_t)N_NODES * N_FEAT];
// weights: single fp16 (B-side); layer l n-major [512n][512k] at l*512*512
__device__ __align__(256) __half g_B[4 * 512 * 512];
// output weights keep hi/lo (3-term out GEMM, negligible error)
__device__ __align__(256) __half g_Woh[64 * JK_DIM];
__device__ __align__(256) __half g_Wol[64 * JK_DIM];

// ---------------- helpers ---------------------------------------------------
__device__ __forceinline__ unsigned su32(const void* p) {
    unsigned a;
    asm("{ .reg .u64 t; cvta.to.shared.u64 t, %1; cvt.u32.u64 %0, t; }"
        : "=r"(a) : "l"(p));
    return a;
}

__device__ __forceinline__ void cp16(unsigned d, const void* s, unsigned sz) {
    asm volatile("cp.async.cg.shared.global [%0], [%1], 16, %2;"
                 :: "r"(d), "l"(s), "r"(sz) : "memory");
}
#define CP_COMMIT asm volatile("cp.async.commit_group;" ::: "memory")
#define CP_WAIT0  asm volatile("cp.async.wait_group 0;" ::: "memory")

#define LDSM4(r, a) \
    asm volatile("ldmatrix.sync.aligned.m8n8.x4.shared.b16 {%0,%1,%2,%3}, [%4];" \
        : "=r"((r)[0]), "=r"((r)[1]), "=r"((r)[2]), "=r"((r)[3]) : "r"(a))

__device__ __forceinline__ void mma_f16(float* c, const unsigned* a,
                                        unsigned b0, unsigned b1) {
    asm volatile("mma.sync.aligned.m16n8k16.row.col.f32.f16.f16.f32 "
        "{%0,%1,%2,%3}, {%4,%5,%6,%7}, {%8,%9}, {%0,%1,%2,%3};"
        : "+f"(c[0]), "+f"(c[1]), "+f"(c[2]), "+f"(c[3])
        : "r"(a[0]), "r"(a[1]), "r"(a[2]), "r"(a[3]), "r"(b0), "r"(b1));
}

// fp16 hi/lo split of two floats, packed as half2 words
__device__ __forceinline__ unsigned split_pack_h(float a, float b,
                                                 unsigned& lo_out) {
    __half2 h, l;
    h.x = __float2half_rn(a);
    h.y = __float2half_rn(b);
    l.x = __float2half_rn(a - __half2float(h.x));
    l.y = __float2half_rn(b - __half2float(h.y));
    lo_out = *reinterpret_cast<unsigned*>(&l);
    return *reinterpret_cast<unsigned*>(&h);
}

__device__ __forceinline__ float2 h2f2(unsigned bits) {
    return __half22float2(*reinterpret_cast<__half2*>(&bits));
}

// ---------------- preprocessing kernels -----------------------------------
__global__ void zero_cnt_kernel() {
    int i = blockIdx.x * blockDim.x + threadIdx.x;
    if (i < N_NODES) g_cnt[i] = 0;
}

__global__ void count_kernel(const int* __restrict__ dst) {
    int i = blockIdx.x * blockDim.x + threadIdx.x;
    if (i < N_EDGES) atomicAdd(&g_cnt[dst[i]], 1);
}

__global__ void dinv_kernel() {
    int i = blockIdx.x * blockDim.x + threadIdx.x;
    if (i < N_NODES) {
        float deg = (float)g_cnt[i] + 1.0f;
        float di  = rsqrtf(deg);
        g_dinv[i]  = di;
        g_selfn[i] = di * di;
    }
}

__global__ __launch_bounds__(1024)
void scan1_kernel() {
    __shared__ int sh[1024];
    int b = blockIdx.x, t = threadIdx.x;
    int idx = b * 4096 + t * 4;
    int s = 0;
    if (idx + 3 < N_NODES) {
        int4 v = *(const int4*)&g_cnt[idx];
        s = v.x + v.y + v.z + v.w;
    } else {
        for (int j = 0; j < 4; j++) if (idx + j < N_NODES) s += g_cnt[idx + j];
    }
    sh[t] = s;
    __syncthreads();
    for (int off = 512; off > 0; off >>= 1) {
        if (t < off) sh[t] += sh[t + off];
        __syncthreads();
    }
    if (t == 0) g_bsum[b] = sh[0];
}

__global__ void scan2_kernel(int nblk) {
    if (threadIdx.x == 0) {
        int acc = 0;
        for (int i = 0; i < nblk; i++) { g_boff[i] = acc; acc += g_bsum[i]; }
        g_off[N_NODES] = acc;
    }
}

__global__ __launch_bounds__(1024)
void scan3_kernel() {
    __shared__ int sh[1024];
    int b = blockIdx.x, t = threadIdx.x;
    int idx = b * 4096 + t * 4;
    int c0 = 0, c1 = 0, c2 = 0, c3 = 0;
    if (idx + 3 < N_NODES) {
        int4 v = *(const int4*)&g_cnt[idx];
        c0 = v.x; c1 = v.y; c2 = v.z; c3 = v.w;
    } else {
        if (idx + 0 < N_NODES) c0 = g_cnt[idx + 0];
        if (idx + 1 < N_NODES) c1 = g_cnt[idx + 1];
        if (idx + 2 < N_NODES) c2 = g_cnt[idx + 2];
        if (idx + 3 < N_NODES) c3 = g_cnt[idx + 3];
    }
    int s = c0 + c1 + c2 + c3;
    sh[t] = s;
    __syncthreads();
    for (int off = 1; off < 1024; off <<= 1) {
        int v = (t >= off) ? sh[t - off] : 0;
        __syncthreads();
        sh[t] += v;
        __syncthreads();
    }
    int excl = g_boff[b] + sh[t] - s;
    int4 ov = make_int4(excl, excl + c0, excl + c0 + c1, excl + c0 + c1 + c2);
    if (idx + 3 < N_NODES) {
        *(int4*)&g_off[idx] = ov;
        *(int4*)&g_cur[idx] = ov;
    } else {
        int o[4] = {ov.x, ov.y, ov.z, ov.w};
        for (int j = 0; j < 4; j++)
            if (idx + j < N_NODES) { g_off[idx + j] = o[j]; g_cur[idx + j] = o[j]; }
    }
}

__global__ void fill_kernel(const int* __restrict__ src, const int* __restrict__ dst) {
    int i = blockIdx.x * blockDim.x + threadIdx.x;
    if (i < N_EDGES) {
        int s = src[i], d = dst[i];
        int pos = atomicAdd(&g_cur[d], 1);
        g_edge[pos] = make_int2(s, __float_as_int(g_dinv[s] * g_dinv[d]));
    }
}

// ---------------- operand packing ------------------------------------------
__global__ void convert_x_kernel(const float* __restrict__ x) {
    size_t i = ((size_t)blockIdx.x * blockDim.x + threadIdx.x) * 4;
    if (i >= (size_t)N_NODES * N_FEAT) return;
    float4 v = *(const float4*)(x + i);
    unsigned l01, l23;
    unsigned h01 = split_pack_h(v.x, v.y, l01);
    unsigned h23 = split_pack_h(v.z, v.w, l23);
    *(uint2*)&g_xh[i] = make_uint2(h01, h23);
    *(uint2*)&g_xl[i] = make_uint2(l01, l23);
}

// B slabs: layer l n-major [512][512]; n<256 gc cols, n>=256 lin cols
__global__ void pack_w_kernel(const float* __restrict__ gcW0,
                              const float* __restrict__ linW0,
                              const float* __restrict__ convsW,
                              const float* __restrict__ linsW) {
    int i = blockIdx.x * blockDim.x + threadIdx.x;
    if (i >= 4 * 512 * 512) return;
    int l = i >> 18, rem = i & 262143, n = rem >> 9, k = rem & 511;
    int Kl = l ? N_HID : N_FEAT;
    if (k >= Kl) return;
    const float* W;
    if (l == 0) W = (n < 256) ? gcW0 : linW0;
    else        W = ((n < 256) ? convsW : linsW) + (l - 1) * N_HID * N_HID;
    g_B[i] = __float2half_rn(W[k * N_HID + (n & 255)]);
}

// out_W packed n-major [64][1024] hi/lo, rows 40..63 zero
__global__ void pack_wo_kernel(const float* __restrict__ outW) {
    int i = blockIdx.x * blockDim.x + threadIdx.x;
    if (i >= 64 * JK_DIM) return;
    int n = i >> 10, k = i & 1023;
    float v = (n < N_CLASS) ? outW[k * N_CLASS + n] : 0.f;
    __half h = __float2half_rn(v);
    g_Woh[i] = h;
    g_Wol[i] = __float2half_rn(v - __half2float(h));
}

// ---------------- fp16x2 GEMM: tile 128M x 64N, 4 warps, 4 CTAs/SM --------
// per 32-k chunk buffer: A hi (10240) + A lo (10240) + B (5120) = 25600
#define SM_ARR 10240
#define SM_BUF 25600

__global__ __launch_bounds__(128, 4)
void gemm_f16x2_kernel(const __half* __restrict__ Ah,
                       const __half* __restrict__ Al,
                       const __half* __restrict__ Bw,
                       __half* __restrict__ Chw, __half* __restrict__ Clin,
                       int M, int K, int lda)
{
    extern __shared__ char smem[];
    const unsigned sbase = su32(smem);
    int tid  = threadIdx.x;
    int lane = tid & 31;
    int wid  = tid >> 5;
    int row0 = blockIdx.y * 128;
    int col0 = blockIdx.x * 64;          // 0..511 over concat(hw,lin)
    int warpM = (wid >> 1) * 64;
    int warpN = (wid & 1) * 32;

    float acc[4][4][4];
    #pragma unroll
    for (int a = 0; a < 4; a++)
        #pragma unroll
        for (int b = 0; b < 4; b++)
            #pragma unroll
            for (int c = 0; c < 4; c++) acc[a][b][c] = 0.f;

    auto stage = [&](int buf, int k0) {
        #pragma unroll
        for (int t = 0; t < 10; t++) {
            int i = tid + t * 128;
            unsigned dst; const __half* src; unsigned sz = 16;
            if (i < 1024) {
                int arr = i >> 9, rem = i & 511, r = rem >> 2, c = rem & 3;
                dst = sbase + buf * SM_BUF + arr * SM_ARR + r * 80 + c * 16;
                int gr = row0 + r;
                if (gr >= M) { gr = M - 1; sz = 0; }
                src = (arr ? Al : Ah) + (size_t)gr * lda + k0 + c * 8;
            } else {
                int j = i - 1024;                 // 0..255
                int r = j >> 2, c = j & 3;        // 64 B rows
                dst = sbase + buf * SM_BUF + 2 * SM_ARR + r * 80 + c * 16;
                src = Bw + (size_t)(col0 + r) * 512 + k0 + c * 8;
            }
            cp16(dst, src, sz);
        }
    };

    stage(0, 0);
    CP_COMMIT;

    const int nch = K >> 5;
    for (int ch = 0; ch < nch; ch++) {
        CP_WAIT0;
        __syncthreads();
        if (ch + 1 < nch) {
            stage((ch + 1) & 1, (ch + 1) << 5);
            CP_COMMIT;
        }

        unsigned abase = sbase + (ch & 1) * SM_BUF;
        unsigned bbase = abase + 2 * SM_ARR;
        int lrow = lane & 15;
        int lk16 = (lane >> 4) * 16;

        #pragma unroll
        for (int ks = 0; ks < 2; ks++) {
            unsigned ah[4][4], al[4][4];
            #pragma unroll
            for (int mt = 0; mt < 4; mt++) {
                unsigned adr = abase + (warpM + mt * 16 + lrow) * 80 + ks * 32 + lk16;
                LDSM4(ah[mt], adr);
                LDSM4(al[mt], adr + SM_ARR);
            }
            unsigned bb[2][4];
            #pragma unroll
            for (int g = 0; g < 2; g++) {
                unsigned adr = bbase + (warpN + g * 16 + lrow) * 80 + ks * 32 + lk16;
                LDSM4(bb[g], adr);
            }
            #pragma unroll
            for (int mt = 0; mt < 4; mt++)
                #pragma unroll
                for (int nt = 0; nt < 4; nt++) {
                    int g = nt >> 1, o = nt & 1;
                    mma_f16(acc[mt][nt], ah[mt], bb[g][o], bb[g][2 + o]);
                }
            #pragma unroll
            for (int mt = 0; mt < 4; mt++)
                #pragma unroll
                for (int nt = 0; nt < 4; nt++) {
                    int g = nt >> 1, o = nt & 1;
                    mma_f16(acc[mt][nt], al[mt], bb[g][o], bb[g][2 + o]);
                }
        }
    }

    // epilogue: fp16 store (half2 per acc pair)
    __half* Cg = (col0 < 256) ? Chw : Clin;
    int cb = col0 & 255;
    #pragma unroll
    for (int mt = 0; mt < 4; mt++)
        #pragma unroll
        for (int nt = 0; nt < 4; nt++) {
            int r = row0 + warpM + mt * 16 + (lane >> 2);
            int c = cb + warpN + nt * 8 + (lane & 3) * 2;
            if (r < M) {
                __half2 v; v.x = __float2half_rn(acc[mt][nt][0]);
                           v.y = __float2half_rn(acc[mt][nt][1]);
                *(__half2*)&Cg[(size_t)r * N_HID + c] = v;
            }
            if (r + 8 < M) {
                __half2 v; v.x = __float2half_rn(acc[mt][nt][2]);
                           v.y = __float2half_rn(acc[mt][nt][3]);
                *(__half2*)&Cg[(size_t)(r + 8) * N_HID + c] = v;
            }
        }
}

// ---------------- fused GCN aggregation epilogue ---------------------------
// 32 threads/block, thread owns 8 halfs (uint4 = 16B gathers); fp32 math
__global__ __launch_bounds__(32)
void agg_kernel(const __half* __restrict__ hw, const __half* __restrict__ lin,
                const float* __restrict__ gcb, const float* __restrict__ linb,
                int slot)
{
    int n  = blockIdx.x;
    int f8 = threadIdx.x * 8;
    int beg = g_off[n], end = g_off[n + 1];

    float acc[8];
    #pragma unroll
    for (int j = 0; j < 8; j++) acc[j] = 0.f;

    int e = beg;
    for (; e + 3 < end; e += 4) {
        int2 p0 = g_edge[e],     p1 = g_edge[e + 1];
        int2 p2 = g_edge[e + 2], p3 = g_edge[e + 3];
        uint4 v0 = *(const uint4*)&hw[(size_t)p0.x * N_HID + f8];
        uint4 v1 = *(const uint4*)&hw[(size_t)p1.x * N_HID + f8];
        uint4 v2 = *(const uint4*)&hw[(size_t)p2.x * N_HID + f8];
        uint4 v3 = *(const uint4*)&hw[(size_t)p3.x * N_HID + f8];
        float c0 = __int_as_float(p0.y), c1 = __int_as_float(p1.y);
        float c2 = __int_as_float(p2.y), c3 = __int_as_float(p3.y);
        const unsigned* w0 = &v0.x; const unsigned* w1 = &v1.x;
        const unsigned* w2 = &v2.x; const unsigned* w3 = &v3.x;
        #pragma unroll
        for (int j = 0; j < 4; j++) {
            float2 f0 = h2f2(w0[j]), f1 = h2f2(w1[j]);
            float2 f2 = h2f2(w2[j]), f3 = h2f2(w3[j]);
            acc[2*j]   += c0 * f0.x + c1 * f1.x + c2 * f2.x + c3 * f3.x;
            acc[2*j+1] += c0 * f0.y + c1 * f1.y + c2 * f2.y + c3 * f3.y;
        }
    }
    for (; e < end; e++) {
        int2 p = g_edge[e];
        uint4 v = *(const uint4*)&hw[(size_t)p.x * N_HID + f8];
        float c = __int_as_float(p.y);
        const unsigned* w = &v.x;
        #pragma unroll
        for (int j = 0; j < 4; j++) {
            float2 f = h2f2(w[j]);
            acc[2*j]   += c * f.x;
            acc[2*j+1] += c * f.y;
        }
    }

    float sn = g_selfn[n];
    uint4 vs = *(const uint4*)&hw [(size_t)n * N_HID + f8];
    uint4 vl = *(const uint4*)&lin[(size_t)n * N_HID + f8];
    float4 bg0 = *(const float4*)&gcb[f8];
    float4 bg1 = *(const float4*)&gcb[f8 + 4];
    float4 bl0 = *(const float4*)&linb[f8];
    float4 bl1 = *(const float4*)&linb[f8 + 4];
    float bgv[8] = {bg0.x, bg0.y, bg0.z, bg0.w, bg1.x, bg1.y, bg1.z, bg1.w};
    float blv[8] = {bl0.x, bl0.y, bl0.z, bl0.w, bl1.x, bl1.y, bl1.z, bl1.w};

    const unsigned* ws = &vs.x;
    const unsigned* wl = &vl.x;
    unsigned hh[4], ll[4];
    #pragma unroll
    for (int j = 0; j < 4; j++) {
        float2 fs = h2f2(ws[j]);
        float2 fl = h2f2(wl[j]);
        float r0 = fmaxf(acc[2*j]   + sn * fs.x + bgv[2*j]   + fl.x + blv[2*j],   0.f);
        float r1 = fmaxf(acc[2*j+1] + sn * fs.y + bgv[2*j+1] + fl.y + blv[2*j+1], 0.f);
        hh[j] = split_pack_h(r0, r1, ll[j]);
    }
    size_t o = (size_t)n * JK_DIM + slot * N_HID + f8;
    *(uint4*)&g_jkh[o] = make_uint4(hh[0], hh[1], hh[2], hh[3]);
    *(uint4*)&g_jkl[o] = make_uint4(ll[0], ll[1], ll[2], ll[3]);
}

// ---------------- output GEMM (fp16 3-term, negligible error) --------------
#define OSM_A  10240
#define OSM_B  5120
#define OSM_BUF (2 * OSM_A + 2 * OSM_B)   // 30720

__global__ __launch_bounds__(256)
void out_mma_kernel(const float* __restrict__ bias, float* __restrict__ out)
{
    extern __shared__ char smem[];
    const unsigned sbase = su32(smem);
    int tid  = threadIdx.x;
    int lane = tid & 31;
    int wid  = tid >> 5;
    int row0 = blockIdx.x * 128;

    float acc[5][4];
    #pragma unroll
    for (int a = 0; a < 5; a++)
        #pragma unroll
        for (int c = 0; c < 4; c++) acc[a][c] = 0.f;

    auto stage = [&](int buf, int k0) {
        #pragma unroll
        for (int t = 0; t < 6; t++) {
            int i = tid + t * 256;
            unsigned dst; const __half* src; unsigned sz = 16;
            if (i < 1024) {
                int hl = i >> 9, rem = i & 511, r = rem >> 2, c = rem & 3;
                int gr = row0 + r;
                if (gr >= N_NODES) { gr = N_NODES - 1; sz = 0; }
                src = (hl ? g_jkl : g_jkh) + (size_t)gr * JK_DIM + k0 + c * 8;
                dst = sbase + buf * OSM_BUF + hl * OSM_A + r * 80 + c * 16;
            } else {
                int j = i - 1024;
                int hl = j >> 8, rem = j & 255, r = rem >> 2, c = rem & 3;
                src = (hl ? g_Wol : g_Woh) + (size_t)r * JK_DIM + k0 + c * 8;
                dst = sbase + buf * OSM_BUF + 2 * OSM_A + hl * OSM_B + r * 80 + c * 16;
            }
            cp16(dst, src, sz);
        }
    };

    stage(0, 0);
    CP_COMMIT;

    const int nch = JK_DIM / 32;
    for (int ch = 0; ch < nch; ch++) {
        CP_WAIT0;
        __syncthreads();
        if (ch + 1 < nch) {
            stage((ch + 1) & 1, (ch + 1) * 32);
            CP_COMMIT;
        }

        unsigned abase = sbase + (ch & 1) * OSM_BUF;
        unsigned bbase = abase + 2 * OSM_A;
        int lrow = lane & 15;
        int lk16 = (lane >> 4) * 16;

        #pragma unroll
        for (int ks = 0; ks < 2; ks++) {
            unsigned ah[4], al[4];
            unsigned adr = abase + (wid * 16 + lrow) * 80 + ks * 32 + lk16;
            LDSM4(ah, adr);
            LDSM4(al, adr + OSM_A);
            unsigned bh[3][4], bl[3][4];
            #pragma unroll
            for (int g = 0; g < 3; g++) {
                unsigned badr = bbase + (g * 16 + lrow) * 80 + ks * 32 + lk16;
                LDSM4(bh[g], badr);
                LDSM4(bl[g], badr + OSM_B);
            }
            #pragma unroll
            for (int nt = 0; nt < 5; nt++) {
                int g = nt >> 1, o = nt & 1;
                mma_f16(acc[nt], ah, bh[g][o], bh[g][2 + o]);
            }
            #pragma unroll
            for (int nt = 0; nt < 5; nt++) {
                int g = nt >> 1, o = nt & 1;
                mma_f16(acc[nt], ah, bl[g][o], bl[g][2 + o]);
            }
            #pragma unroll
            for (int nt = 0; nt < 5; nt++) {
                int g = nt >> 1, o = nt & 1;
                mma_f16(acc[nt], al, bh[g][o], bh[g][2 + o]);
            }
        }
    }

    #pragma unroll
    for (int nt = 0; nt < 5; nt++) {
        int c = nt * 8 + (lane & 3) * 2;
        float2 bv = make_float2(bias[c], bias[c + 1]);
        int r = row0 + wid * 16 + (lane >> 2);
        if (r < N_NODES)
            *(float2*)&out[(size_t)r * N_CLASS + c] =
                make_float2(acc[nt][0] + bv.x, acc[nt][1] + bv.y);
        if (r + 8 < N_NODES)
            *(float2*)&out[(size_t)(r + 8) * N_CLASS + c] =
                make_float2(acc[nt][2] + bv.x, acc[nt][3] + bv.y);
    }
}

// ---------------- launch ---------------------------------------------------
extern "C" void kernel_launch(void* const* d_in, const int* in_sizes, int n_in,
                              void* d_out, int out_size)
{
    const float* x        = (const float*)d_in[0];
    const int*   edge     = (const int*)  d_in[1];
    const float* in_gc_W  = (const float*)d_in[2];
    const float* in_gc_b  = (const float*)d_in[3];
    const float* in_lin_W = (const float*)d_in[4];
    const float* in_lin_b = (const float*)d_in[5];
    const float* convs_W  = (const float*)d_in[6];
    const float* convs_b  = (const float*)d_in[7];
    const float* lins_W   = (const float*)d_in[8];
    const float* lins_b   = (const float*)d_in[9];
    const float* out_W    = (const float*)d_in[10];
    const float* out_b    = (const float*)d_in[11];
    float*       out      = (float*)d_out;

    const int* src = edge;
    const int* dst = edge + N_EDGES;

    __half *p_hw, *p_lin, *p_xh, *p_xl, *p_jkh, *p_jkl, *p_B;
    cudaGetSymbolAddress((void**)&p_hw,  g_hw);
    cudaGetSymbolAddress((void**)&p_lin, g_lin);
    cudaGetSymbolAddress((void**)&p_xh,  g_xh);
    cudaGetSymbolAddress((void**)&p_xl,  g_xl);
    cudaGetSymbolAddress((void**)&p_jkh, g_jkh);
    cudaGetSymbolAddress((void**)&p_jkl, g_jkl);
    cudaGetSymbolAddress((void**)&p_B,   g_B);

    cudaFuncSetAttribute(gemm_f16x2_kernel,
                         cudaFuncAttributeMaxDynamicSharedMemorySize, 2 * SM_BUF);
    cudaFuncSetAttribute(out_mma_kernel,
                         cudaFuncAttributeMaxDynamicSharedMemorySize, 2 * OSM_BUF);

    dim3 ggrid(8, (N_NODES + 127) / 128);   // 64-wide N blocks over concat 512

    // order: my #4 (profiled under ncu -s 5) = gemm layer 0
    convert_x_kernel<<<(N_NODES * N_FEAT / 4 + 255) / 256, 256>>>(x);
    pack_w_kernel<<<(4 * 512 * 512 + 255) / 256, 256>>>(in_gc_W, in_lin_W,
                                                        convs_W, lins_W);
    zero_cnt_kernel<<<(N_NODES + 255) / 256, 256>>>();
    gemm_f16x2_kernel<<<ggrid, 128, 2 * SM_BUF>>>(      // <- profiled
        p_xh, p_xl, p_B, p_hw, p_lin, N_NODES, N_FEAT, N_FEAT);
    pack_wo_kernel<<<(64 * JK_DIM + 255) / 256, 256>>>(out_W);
    count_kernel<<<(N_EDGES + 255) / 256, 256>>>(dst);
    dinv_kernel<<<(N_NODES + 255) / 256, 256>>>();
    scan1_kernel<<<13, 1024>>>();
    scan2_kernel<<<1, 32>>>(13);
    scan3_kernel<<<13, 1024>>>();
    fill_kernel<<<(N_EDGES + 255) / 256, 256>>>(src, dst);

    agg_kernel<<<N_NODES, 32>>>(p_hw, p_lin, in_gc_b, in_lin_b, 0);

    for (int i = 0; i < N_LAYER - 1; i++) {
        gemm_f16x2_kernel<<<ggrid, 128, 2 * SM_BUF>>>(
            p_jkh + i * N_HID, p_jkl + i * N_HID,
            p_B + (size_t)(i + 1) * 512 * 512,
            p_hw, p_lin, N_NODES, N_HID, JK_DIM);
        agg_kernel<<<N_NODES, 32>>>(p_hw, p_lin,
                                    convs_b + i * N_HID, lins_b + i * N_HID,
                                    i + 1);
    }

    out_mma_kernel<<<(N_NODES + 127) / 128, 256, 2 * OSM_BUF>>>(out_b, out);
}

// round 11
// speedup vs baseline: 1.0274x; 1.0274x over previous
#include <cuda_runtime.h>
#include <cuda_fp16.h>

#define N_NODES 50000
#define N_EDGES 800000
#define N_FEAT  512
#define N_HID   256
#define N_LAYER 4
#define N_CLASS 40
#define JK_DIM  (N_HID * N_LAYER)   // 1024

// ---------------- scratch (device globals; no allocation allowed) ----------
__device__ int   g_cnt[N_NODES];
__device__ int   g_off[N_NODES + 1];
__device__ int   g_cur[N_NODES];
__device__ int   g_bsum[16];
__device__ int   g_boff[16];
__device__ __align__(16) int2 g_edge[N_EDGES];      // {src, coef bits}
__device__ float g_dinv[N_NODES];
__device__ float g_selfn[N_NODES];
// GEMM outputs stored fp16 (gather traffic halved); aggregation math is fp32
__device__ __align__(256) __half g_hw [N_NODES * N_HID];           // 25.6 MB
__device__ __align__(256) __half g_lin[N_NODES * N_HID];           // 25.6 MB
// fp16 hi/lo activation slabs (A-side operands, exact to 2^-22)
__device__ __align__(256) __half g_jkh[(size_t)N_NODES * JK_DIM];
__device__ __align__(256) __half g_jkl[(size_t)N_NODES * JK_DIM];
__device__ __align__(256) __half g_xh[(size_t)N_NODES * N_FEAT];
__device__ __align__(256) __half g_xl[(size_t)N_NODES * N_FEAT];
// weights: single fp16 (B-side); layer l n-major [512n][512k] at l*512*512
__device__ __align__(256) __half g_B[4 * 512 * 512];
// output weights keep hi/lo (3-term out GEMM, negligible error)
__device__ __align__(256) __half g_Woh[64 * JK_DIM];
__device__ __align__(256) __half g_Wol[64 * JK_DIM];

// ---------------- helpers ---------------------------------------------------
__device__ __forceinline__ unsigned su32(const void* p) {
    unsigned a;
    asm("{ .reg .u64 t; cvta.to.shared.u64 t, %1; cvt.u32.u64 %0, t; }"
        : "=r"(a) : "l"(p));
    return a;
}

__device__ __forceinline__ void cp16(unsigned d, const void* s, unsigned sz) {
    asm volatile("cp.async.cg.shared.global [%0], [%1], 16, %2;"
                 :: "r"(d), "l"(s), "r"(sz) : "memory");
}
#define CP_COMMIT asm volatile("cp.async.commit_group;" ::: "memory")
#define CP_WAIT0  asm volatile("cp.async.wait_group 0;" ::: "memory")

#define LDSM4(r, a) \
    asm volatile("ldmatrix.sync.aligned.m8n8.x4.shared.b16 {%0,%1,%2,%3}, [%4];" \
        : "=r"((r)[0]), "=r"((r)[1]), "=r"((r)[2]), "=r"((r)[3]) : "r"(a))

__device__ __forceinline__ void mma_f16(float* c, const unsigned* a,
                                        unsigned b0, unsigned b1) {
    asm volatile("mma.sync.aligned.m16n8k16.row.col.f32.f16.f16.f32 "
        "{%0,%1,%2,%3}, {%4,%5,%6,%7}, {%8,%9}, {%0,%1,%2,%3};"
        : "+f"(c[0]), "+f"(c[1]), "+f"(c[2]), "+f"(c[3])
        : "r"(a[0]), "r"(a[1]), "r"(a[2]), "r"(a[3]), "r"(b0), "r"(b1));
}

// fp16 hi/lo split of two floats, packed as half2 words
__device__ __forceinline__ unsigned split_pack_h(float a, float b,
                                                 unsigned& lo_out) {
    __half2 h, l;
    h.x = __float2half_rn(a);
    h.y = __float2half_rn(b);
    l.x = __float2half_rn(a - __half2float(h.x));
    l.y = __float2half_rn(b - __half2float(h.y));
    lo_out = *reinterpret_cast<unsigned*>(&l);
    return *reinterpret_cast<unsigned*>(&h);
}

__device__ __forceinline__ float2 h2f2(unsigned bits) {
    return __half22float2(*reinterpret_cast<__half2*>(&bits));
}

// ---------------- preprocessing kernels -----------------------------------
__global__ void zero_cnt_kernel() {
    int i = blockIdx.x * blockDim.x + threadIdx.x;
    if (i < N_NODES) g_cnt[i] = 0;
}

__global__ void count_kernel(const int* __restrict__ dst) {
    int i = blockIdx.x * blockDim.x + threadIdx.x;
    if (i < N_EDGES) atomicAdd(&g_cnt[dst[i]], 1);
}

__global__ void dinv_kernel() {
    int i = blockIdx.x * blockDim.x + threadIdx.x;
    if (i < N_NODES) {
        float deg = (float)g_cnt[i] + 1.0f;
        float di  = rsqrtf(deg);
        g_dinv[i]  = di;
        g_selfn[i] = di * di;
    }
}

__global__ __launch_bounds__(1024)
void scan1_kernel() {
    __shared__ int sh[1024];
    int b = blockIdx.x, t = threadIdx.x;
    int idx = b * 4096 + t * 4;
    int s = 0;
    if (idx + 3 < N_NODES) {
        int4 v = *(const int4*)&g_cnt[idx];
        s = v.x + v.y + v.z + v.w;
    } else {
        for (int j = 0; j < 4; j++) if (idx + j < N_NODES) s += g_cnt[idx + j];
    }
    sh[t] = s;
    __syncthreads();
    for (int off = 512; off > 0; off >>= 1) {
        if (t < off) sh[t] += sh[t + off];
        __syncthreads();
    }
    if (t == 0) g_bsum[b] = sh[0];
}

__global__ void scan2_kernel(int nblk) {
    if (threadIdx.x == 0) {
        int acc = 0;
        for (int i = 0; i < nblk; i++) { g_boff[i] = acc; acc += g_bsum[i]; }
        g_off[N_NODES] = acc;
    }
}

__global__ __launch_bounds__(1024)
void scan3_kernel() {
    __shared__ int sh[1024];
    int b = blockIdx.x, t = threadIdx.x;
    int idx = b * 4096 + t * 4;
    int c0 = 0, c1 = 0, c2 = 0, c3 = 0;
    if (idx + 3 < N_NODES) {
        int4 v = *(const int4*)&g_cnt[idx];
        c0 = v.x; c1 = v.y; c2 = v.z; c3 = v.w;
    } else {
        if (idx + 0 < N_NODES) c0 = g_cnt[idx + 0];
        if (idx + 1 < N_NODES) c1 = g_cnt[idx + 1];
        if (idx + 2 < N_NODES) c2 = g_cnt[idx + 2];
        if (idx + 3 < N_NODES) c3 = g_cnt[idx + 3];
    }
    int s = c0 + c1 + c2 + c3;
    sh[t] = s;
    __syncthreads();
    for (int off = 1; off < 1024; off <<= 1) {
        int v = (t >= off) ? sh[t - off] : 0;
        __syncthreads();
        sh[t] += v;
        __syncthreads();
    }
    int excl = g_boff[b] + sh[t] - s;
    int4 ov = make_int4(excl, excl + c0, excl + c0 + c1, excl + c0 + c1 + c2);
    if (idx + 3 < N_NODES) {
        *(int4*)&g_off[idx] = ov;
        *(int4*)&g_cur[idx] = ov;
    } else {
        int o[4] = {ov.x, ov.y, ov.z, ov.w};
        for (int j = 0; j < 4; j++)
            if (idx + j < N_NODES) { g_off[idx + j] = o[j]; g_cur[idx + j] = o[j]; }
    }
}

__global__ void fill_kernel(const int* __restrict__ src, const int* __restrict__ dst) {
    int i = blockIdx.x * blockDim.x + threadIdx.x;
    if (i < N_EDGES) {
        int s = src[i], d = dst[i];
        int pos = atomicAdd(&g_cur[d], 1);
        g_edge[pos] = make_int2(s, __float_as_int(g_dinv[s] * g_dinv[d]));
    }
}

// ---------------- operand packing ------------------------------------------
__global__ void convert_x_kernel(const float* __restrict__ x) {
    size_t i = ((size_t)blockIdx.x * blockDim.x + threadIdx.x) * 4;
    if (i >= (size_t)N_NODES * N_FEAT) return;
    float4 v = *(const float4*)(x + i);
    unsigned l01, l23;
    unsigned h01 = split_pack_h(v.x, v.y, l01);
    unsigned h23 = split_pack_h(v.z, v.w, l23);
    *(uint2*)&g_xh[i] = make_uint2(h01, h23);
    *(uint2*)&g_xl[i] = make_uint2(l01, l23);
}

// B slabs: layer l n-major [512][512]; n<256 gc cols, n>=256 lin cols
__global__ void pack_w_kernel(const float* __restrict__ gcW0,
                              const float* __restrict__ linW0,
                              const float* __restrict__ convsW,
                              const float* __restrict__ linsW) {
    int i = blockIdx.x * blockDim.x + threadIdx.x;
    if (i >= 4 * 512 * 512) return;
    int l = i >> 18, rem = i & 262143, n = rem >> 9, k = rem & 511;
    int Kl = l ? N_HID : N_FEAT;
    if (k >= Kl) return;
    const float* W;
    if (l == 0) W = (n < 256) ? gcW0 : linW0;
    else        W = ((n < 256) ? convsW : linsW) + (l - 1) * N_HID * N_HID;
    g_B[i] = __float2half_rn(W[k * N_HID + (n & 255)]);
}

// out_W packed n-major [64][1024] hi/lo, rows 40..63 zero
__global__ void pack_wo_kernel(const float* __restrict__ outW) {
    int i = blockIdx.x * blockDim.x + threadIdx.x;
    if (i >= 64 * JK_DIM) return;
    int n = i >> 10, k = i & 1023;
    float v = (n < N_CLASS) ? outW[k * N_CLASS + n] : 0.f;
    __half h = __float2half_rn(v);
    g_Woh[i] = h;
    g_Wol[i] = __float2half_rn(v - __half2float(h));
}

// ---------------- fp16x2 GEMM: C[M,512] = A[M,K] @ B[K,512] ---------------
// per 32-k chunk buffer: A hi (10240) + A lo (10240) + B (10240)
#define SM_ARR 10240
#define SM_BUF 30720

__global__ __launch_bounds__(256)
void gemm_f16x2_kernel(const __half* __restrict__ Ah,
                       const __half* __restrict__ Al,
                       const __half* __restrict__ Bw,
                       __half* __restrict__ Chw, __half* __restrict__ Clin,
                       int M, int K, int lda)
{
    extern __shared__ char smem[];
    const unsigned sbase = su32(smem);
    int tid  = threadIdx.x;
    int lane = tid & 31;
    int wid  = tid >> 5;
    int row0 = blockIdx.y * 128;
    int col0 = blockIdx.x * 128;
    int warpM = (wid >> 2) * 64;
    int warpN = (wid & 3) * 32;

    float acc[4][4][4];
    #pragma unroll
    for (int a = 0; a < 4; a++)
        #pragma unroll
        for (int b = 0; b < 4; b++)
            #pragma unroll
            for (int c = 0; c < 4; c++) acc[a][b][c] = 0.f;

    auto stage = [&](int buf, int k0) {
        #pragma unroll
        for (int t = 0; t < 6; t++) {
            int i = tid + t * 256;
            int arr = i >> 9, rem = i & 511, r = rem >> 2, c = rem & 3;
            unsigned dst = sbase + buf * SM_BUF + arr * SM_ARR + r * 80 + c * 16;
            const __half* src;
            unsigned sz = 16;
            if (arr < 2) {
                int gr = row0 + r;
                if (gr >= M) { gr = M - 1; sz = 0; }
                src = (arr ? Al : Ah) + (size_t)gr * lda + k0 + c * 8;
            } else {
                src = Bw + (size_t)(col0 + r) * 512 + k0 + c * 8;
            }
            cp16(dst, src, sz);
        }
    };

    stage(0, 0);
    CP_COMMIT;

    const int nch = K >> 5;
    for (int ch = 0; ch < nch; ch++) {
        CP_WAIT0;
        __syncthreads();
        if (ch + 1 < nch) {
            stage((ch + 1) & 1, (ch + 1) << 5);
            CP_COMMIT;
        }

        unsigned abase = sbase + (ch & 1) * SM_BUF;
        unsigned bbase = abase + 2 * SM_ARR;
        int lrow = lane & 15;
        int lk16 = (lane >> 4) * 16;

        #pragma unroll
        for (int ks = 0; ks < 2; ks++) {
            // B fragments for this ks
            unsigned bb[2][4];
            #pragma unroll
            for (int g = 0; g < 2; g++) {
                unsigned adr = bbase + (warpN + g * 16 + lrow) * 80 + ks * 32 + lk16;
                LDSM4(bb[g], adr);
            }
            // A fragments double-buffered in m-halves (2 m-tiles per batch)
            unsigned ah[2][2][4], al[2][2][4];
            #pragma unroll
            for (int m2 = 0; m2 < 2; m2++) {
                unsigned adr = abase + (warpM + m2 * 16 + lrow) * 80 + ks * 32 + lk16;
                LDSM4(ah[0][m2], adr);
                LDSM4(al[0][m2], adr + SM_ARR);
            }
            #pragma unroll
            for (int mh = 0; mh < 2; mh++) {
                if (mh == 0) {
                    // prefetch second m-half while first half's MMAs run
                    #pragma unroll
                    for (int m2 = 0; m2 < 2; m2++) {
                        unsigned adr = abase + (warpM + (2 + m2) * 16 + lrow) * 80
                                       + ks * 32 + lk16;
                        LDSM4(ah[1][m2], adr);
                        LDSM4(al[1][m2], adr + SM_ARR);
                    }
                }
                #pragma unroll
                for (int m2 = 0; m2 < 2; m2++) {
                    int mt = mh * 2 + m2;
                    #pragma unroll
                    for (int nt = 0; nt < 4; nt++) {
                        int g = nt >> 1, o = nt & 1;
                        mma_f16(acc[mt][nt], ah[mh][m2], bb[g][o], bb[g][2 + o]);
                    }
                    #pragma unroll
                    for (int nt = 0; nt < 4; nt++) {
                        int g = nt >> 1, o = nt & 1;
                        mma_f16(acc[mt][nt], al[mh][m2], bb[g][o], bb[g][2 + o]);
                    }
                }
            }
        }
    }

    // epilogue: fp16 store (half2 per acc pair)
    __half* Cg = (col0 < 256) ? Chw : Clin;
    int cb = (col0 < 256) ? col0 : (col0 - 256);
    #pragma unroll
    for (int mt = 0; mt < 4; mt++)
        #pragma unroll
        for (int nt = 0; nt < 4; nt++) {
            int r = row0 + warpM + mt * 16 + (lane >> 2);
            int c = cb + warpN + nt * 8 + (lane & 3) * 2;
            if (r < M) {
                __half2 v; v.x = __float2half_rn(acc[mt][nt][0]);
                           v.y = __float2half_rn(acc[mt][nt][1]);
                *(__half2*)&Cg[(size_t)r * N_HID + c] = v;
            }
            if (r + 8 < M) {
                __half2 v; v.x = __float2half_rn(acc[mt][nt][2]);
                           v.y = __float2half_rn(acc[mt][nt][3]);
                *(__half2*)&Cg[(size_t)(r + 8) * N_HID + c] = v;
            }
        }
}

// ---------------- fused GCN aggregation epilogue ---------------------------
// 32 threads/block, thread owns 8 halfs (uint4 = 16B gathers); fp32 math
__global__ __launch_bounds__(32)
void agg_kernel(const __half* __restrict__ hw, const __half* __restrict__ lin,
                const float* __restrict__ gcb, const float* __restrict__ linb,
                int slot)
{
    int n  = blockIdx.x;
    int f8 = threadIdx.x * 8;
    int beg = g_off[n], end = g_off[n + 1];

    float acc[8];
    #pragma unroll
    for (int j = 0; j < 8; j++) acc[j] = 0.f;

    int e = beg;
    for (; e + 3 < end; e += 4) {
        int2 p0 = g_edge[e],     p1 = g_edge[e + 1];
        int2 p2 = g_edge[e + 2], p3 = g_edge[e + 3];
        uint4 v0 = *(const uint4*)&hw[(size_t)p0.x * N_HID + f8];
        uint4 v1 = *(const uint4*)&hw[(size_t)p1.x * N_HID + f8];
        uint4 v2 = *(const uint4*)&hw[(size_t)p2.x * N_HID + f8];
        uint4 v3 = *(const uint4*)&hw[(size_t)p3.x * N_HID + f8];
        float c0 = __int_as_float(p0.y), c1 = __int_as_float(p1.y);
        float c2 = __int_as_float(p2.y), c3 = __int_as_float(p3.y);
        const unsigned* w0 = &v0.x; const unsigned* w1 = &v1.x;
        const unsigned* w2 = &v2.x; const unsigned* w3 = &v3.x;
        #pragma unroll
        for (int j = 0; j < 4; j++) {
            float2 f0 = h2f2(w0[j]), f1 = h2f2(w1[j]);
            float2 f2 = h2f2(w2[j]), f3 = h2f2(w3[j]);
            acc[2*j]   += c0 * f0.x + c1 * f1.x + c2 * f2.x + c3 * f3.x;
            acc[2*j+1] += c0 * f0.y + c1 * f1.y + c2 * f2.y + c3 * f3.y;
        }
    }
    for (; e < end; e++) {
        int2 p = g_edge[e];
        uint4 v = *(const uint4*)&hw[(size_t)p.x * N_HID + f8];
        float c = __int_as_float(p.y);
        const unsigned* w = &v.x;
        #pragma unroll
        for (int j = 0; j < 4; j++) {
            float2 f = h2f2(w[j]);
            acc[2*j]   += c * f.x;
            acc[2*j+1] += c * f.y;
        }
    }

    float sn = g_selfn[n];
    uint4 vs = *(const uint4*)&hw [(size_t)n * N_HID + f8];
    uint4 vl = *(const uint4*)&lin[(size_t)n * N_HID + f8];
    float4 bg0 = *(const float4*)&gcb[f8];
    float4 bg1 = *(const float4*)&gcb[f8 + 4];
    float4 bl0 = *(const float4*)&linb[f8];
    float4 bl1 = *(const float4*)&linb[f8 + 4];
    float bgv[8] = {bg0.x, bg0.y, bg0.z, bg0.w, bg1.x, bg1.y, bg1.z, bg1.w};
    float blv[8] = {bl0.x, bl0.y, bl0.z, bl0.w, bl1.x, bl1.y, bl1.z, bl1.w};

    const unsigned* ws = &vs.x;
    const unsigned* wl = &vl.x;
    unsigned hh[4], ll[4];
    #pragma unroll
    for (int j = 0; j < 4; j++) {
        float2 fs = h2f2(ws[j]);
        float2 fl = h2f2(wl[j]);
        float r0 = fmaxf(acc[2*j]   + sn * fs.x + bgv[2*j]   + fl.x + blv[2*j],   0.f);
        float r1 = fmaxf(acc[2*j+1] + sn * fs.y + bgv[2*j+1] + fl.y + blv[2*j+1], 0.f);
        hh[j] = split_pack_h(r0, r1, ll[j]);
    }
    size_t o = (size_t)n * JK_DIM + slot * N_HID + f8;
    *(uint4*)&g_jkh[o] = make_uint4(hh[0], hh[1], hh[2], hh[3]);
    *(uint4*)&g_jkl[o] = make_uint4(ll[0], ll[1], ll[2], ll[3]);
}

// ---------------- output GEMM (fp16 3-term, negligible error) --------------
#define OSM_A  10240
#define OSM_B  5120
#define OSM_BUF (2 * OSM_A + 2 * OSM_B)   // 30720

__global__ __launch_bounds__(256)
void out_mma_kernel(const float* __restrict__ bias, float* __restrict__ out)
{
    extern __shared__ char smem[];
    const unsigned sbase = su32(smem);
    int tid  = threadIdx.x;
    int lane = tid & 31;
    int wid  = tid >> 5;
    int row0 = blockIdx.x * 128;

    float acc[5][4];
    #pragma unroll
    for (int a = 0; a < 5; a++)
        #pragma unroll
        for (int c = 0; c < 4; c++) acc[a][c] = 0.f;

    auto stage = [&](int buf, int k0) {
        #pragma unroll
        for (int t = 0; t < 6; t++) {
            int i = tid + t * 256;
            unsigned dst; const __half* src; unsigned sz = 16;
            if (i < 1024) {
                int hl = i >> 9, rem = i & 511, r = rem >> 2, c = rem & 3;
                int gr = row0 + r;
                if (gr >= N_NODES) { gr = N_NODES - 1; sz = 0; }
                src = (hl ? g_jkl : g_jkh) + (size_t)gr * JK_DIM + k0 + c * 8;
                dst = sbase + buf * OSM_BUF + hl * OSM_A + r * 80 + c * 16;
            } else {
                int j = i - 1024;
                int hl = j >> 8, rem = j & 255, r = rem >> 2, c = rem & 3;
                src = (hl ? g_Wol : g_Woh) + (size_t)r * JK_DIM + k0 + c * 8;
                dst = sbase + buf * OSM_BUF + 2 * OSM_A + hl * OSM_B + r * 80 + c * 16;
            }
            cp16(dst, src, sz);
        }
    };

    stage(0, 0);
    CP_COMMIT;

    const int nch = JK_DIM / 32;
    for (int ch = 0; ch < nch; ch++) {
        CP_WAIT0;
        __syncthreads();
        if (ch + 1 < nch) {
            stage((ch + 1) & 1, (ch + 1) * 32);
            CP_COMMIT;
        }

        unsigned abase = sbase + (ch & 1) * OSM_BUF;
        unsigned bbase = abase + 2 * OSM_A;
        int lrow = lane & 15;
        int lk16 = (lane >> 4) * 16;

        #pragma unroll
        for (int ks = 0; ks < 2; ks++) {
            unsigned ah[4], al[4];
            unsigned adr = abase + (wid * 16 + lrow) * 80 + ks * 32 + lk16;
            LDSM4(ah, adr);
            LDSM4(al, adr + OSM_A);
            unsigned bh[3][4], bl[3][4];
            #pragma unroll
            for (int g = 0; g < 3; g++) {
                unsigned badr = bbase + (g * 16 + lrow) * 80 + ks * 32 + lk16;
                LDSM4(bh[g], badr);
                LDSM4(bl[g], badr + OSM_B);
            }
            #pragma unroll
            for (int nt = 0; nt < 5; nt++) {
                int g = nt >> 1, o = nt & 1;
                mma_f16(acc[nt], ah, bh[g][o], bh[g][2 + o]);
            }
            #pragma unroll
            for (int nt = 0; nt < 5; nt++) {
                int g = nt >> 1, o = nt & 1;
                mma_f16(acc[nt], ah, bl[g][o], bl[g][2 + o]);
            }
            #pragma unroll
            for (int nt = 0; nt < 5; nt++) {
                int g = nt >> 1, o = nt & 1;
                mma_f16(acc[nt], al, bh[g][o], bh[g][2 + o]);
            }
        }
    }

    #pragma unroll
    for (int nt = 0; nt < 5; nt++) {
        int c = nt * 8 + (lane & 3) * 2;
        float2 bv = make_float2(bias[c], bias[c + 1]);
        int r = row0 + wid * 16 + (lane >> 2);
        if (r < N_NODES)
            *(float2*)&out[(size_t)r * N_CLASS + c] =
                make_float2(acc[nt][0] + bv.x, acc[nt][1] + bv.y);
        if (r + 8 < N_NODES)
            *(float2*)&out[(size_t)(r + 8) * N_CLASS + c] =
                make_float2(acc[nt][2] + bv.x, acc[nt][3] + bv.y);
    }
}

// ---------------- launch ---------------------------------------------------
extern "C" void kernel_launch(void* const* d_in, const int* in_sizes, int n_in,
                              void* d_out, int out_size)
{
    const float* x        = (const float*)d_in[0];
    const int*   edge     = (const int*)  d_in[1];
    const float* in_gc_W  = (const float*)d_in[2];
    const float* in_gc_b  = (const float*)d_in[3];
    const float* in_lin_W = (const float*)d_in[4];
    const float* in_lin_b = (const float*)d_in[5];
    const float* convs_W  = (const float*)d_in[6];
    const float* convs_b  = (const float*)d_in[7];
    const float* lins_W   = (const float*)d_in[8];
    const float* lins_b   = (const float*)d_in[9];
    const float* out_W    = (const float*)d_in[10];
    const float* out_b    = (const float*)d_in[11];
    float*       out      = (float*)d_out;

    const int* src = edge;
    const int* dst = edge + N_EDGES;

    __half *p_hw, *p_lin, *p_xh, *p_xl, *p_jkh, *p_jkl, *p_B;
    cudaGetSymbolAddress((void**)&p_hw,  g_hw);
    cudaGetSymbolAddress((void**)&p_lin, g_lin);
    cudaGetSymbolAddress((void**)&p_xh,  g_xh);
    cudaGetSymbolAddress((void**)&p_xl,  g_xl);
    cudaGetSymbolAddress((void**)&p_jkh, g_jkh);
    cudaGetSymbolAddress((void**)&p_jkl, g_jkl);
    cudaGetSymbolAddress((void**)&p_B,   g_B);

    cudaFuncSetAttribute(gemm_f16x2_kernel,
                         cudaFuncAttributeMaxDynamicSharedMemorySize, 2 * SM_BUF);
    cudaFuncSetAttribute(out_mma_kernel,
                         cudaFuncAttributeMaxDynamicSharedMemorySize, 2 * OSM_BUF);

    dim3 ggrid(4, (N_NODES + 127) / 128);

    // order: my #4 (profiled under ncu -s 5) = gemm layer 0
    convert_x_kernel<<<(N_NODES * N_FEAT / 4 + 255) / 256, 256>>>(x);
    pack_w_kernel<<<(4 * 512 * 512 + 255) / 256, 256>>>(in_gc_W, in_lin_W,
                                                        convs_W, lins_W);
    zero_cnt_kernel<<<(N_NODES + 255) / 256, 256>>>();
    gemm_f16x2_kernel<<<ggrid, 256, 2 * SM_BUF>>>(      // <- profiled
        p_xh, p_xl, p_B, p_hw, p_lin, N_NODES, N_FEAT, N_FEAT);
    pack_wo_kernel<<<(64 * JK_DIM + 255) / 256, 256>>>(out_W);
    count_kernel<<<(N_EDGES + 255) / 256, 256>>>(dst);
    dinv_kernel<<<(N_NODES + 255) / 256, 256>>>();
    scan1_kernel<<<13, 1024>>>();
    scan2_kernel<<<1, 32>>>(13);
    scan3_kernel<<<13, 1024>>>();
    fill_kernel<<<(N_EDGES + 255) / 256, 256>>>(src, dst);

    agg_kernel<<<N_NODES, 32>>>(p_hw, p_lin, in_gc_b, in_lin_b, 0);

    for (int i = 0; i < N_LAYER - 1; i++) {
        gemm_f16x2_kernel<<<ggrid, 256, 2 * SM_BUF>>>(
            p_jkh + i * N_HID, p_jkl + i * N_HID,
            p_B + (size_t)(i + 1) * 512 * 512,
            p_hw, p_lin, N_NODES, N_HID, JK_DIM);
        agg_kernel<<<N_NODES, 32>>>(p_hw, p_lin,
                                    convs_b + i * N_HID, lins_b + i * N_HID,
                                    i + 1);
    }

    out_mma_kernel<<<(N_NODES + 127) / 128, 256, 2 * OSM_BUF>>>(out_b, out);
}

// round 12
// speedup vs baseline: 1.2963x; 1.2617x over previous
#include <cuda_runtime.h>
#include <cuda_fp16.h>

#define N_NODES 50000
#define N_EDGES 800000
#define N_FEAT  512
#define N_HID   256
#define N_LAYER 4
#define N_CLASS 40
#define JK_DIM  (N_HID * N_LAYER)   // 1024

// ---------------- scratch (device globals; no allocation allowed) ----------
__device__ int   g_cnt[N_NODES];
__device__ int   g_off[N_NODES + 1];
__device__ int   g_cur[N_NODES];
__device__ int   g_bsum[16];
__device__ int   g_boff[16];
__device__ __align__(16) int2 g_edge[N_EDGES];      // {src, coef bits}
__device__ float g_dinv[N_NODES];
__device__ float g_selfn[N_NODES];
// GEMM outputs stored fp16; aggregation math is fp32
__device__ __align__(256) __half g_hw [N_NODES * N_HID];           // 25.6 MB
__device__ __align__(256) __half g_lin[N_NODES * N_HID];           // 25.6 MB
// jk slab fp16 hi/lo (lo used only by the 3-term output GEMM)
__device__ __align__(256) __half g_jkh[(size_t)N_NODES * JK_DIM];
__device__ __align__(256) __half g_jkl[(size_t)N_NODES * JK_DIM];
__device__ __align__(256) __half g_xh[(size_t)N_NODES * N_FEAT];
// weights: single fp16; layer l n-major [512n][512k] at l*512*512
__device__ __align__(256) __half g_B[4 * 512 * 512];
// output weights keep hi/lo (3-term out GEMM)
__device__ __align__(256) __half g_Woh[64 * JK_DIM];
__device__ __align__(256) __half g_Wol[64 * JK_DIM];

// ---------------- helpers ---------------------------------------------------
__device__ __forceinline__ unsigned su32(const void* p) {
    unsigned a;
    asm("{ .reg .u64 t; cvta.to.shared.u64 t, %1; cvt.u32.u64 %0, t; }"
        : "=r"(a) : "l"(p));
    return a;
}

__device__ __forceinline__ void cp16(unsigned d, const void* s, unsigned sz) {
    asm volatile("cp.async.cg.shared.global [%0], [%1], 16, %2;"
                 :: "r"(d), "l"(s), "r"(sz) : "memory");
}
#define CP_COMMIT asm volatile("cp.async.commit_group;" ::: "memory")
#define CP_WAIT0  asm volatile("cp.async.wait_group 0;" ::: "memory")

#define LDSM4(r, a) \
    asm volatile("ldmatrix.sync.aligned.m8n8.x4.shared.b16 {%0,%1,%2,%3}, [%4];" \
        : "=r"((r)[0]), "=r"((r)[1]), "=r"((r)[2]), "=r"((r)[3]) : "r"(a))

__device__ __forceinline__ void mma_f16(float* c, const unsigned* a,
                                        unsigned b0, unsigned b1) {
    asm volatile("mma.sync.aligned.m16n8k16.row.col.f32.f16.f16.f32 "
        "{%0,%1,%2,%3}, {%4,%5,%6,%7}, {%8,%9}, {%0,%1,%2,%3};"
        : "+f"(c[0]), "+f"(c[1]), "+f"(c[2]), "+f"(c[3])
        : "r"(a[0]), "r"(a[1]), "r"(a[2]), "r"(a[3]), "r"(b0), "r"(b1));
}

__device__ __forceinline__ unsigned split_pack_h(float a, float b,
                                                 unsigned& lo_out) {
    __half2 h, l;
    h.x = __float2half_rn(a);
    h.y = __float2half_rn(b);
    l.x = __float2half_rn(a - __half2float(h.x));
    l.y = __float2half_rn(b - __half2float(h.y));
    lo_out = *reinterpret_cast<unsigned*>(&l);
    return *reinterpret_cast<unsigned*>(&h);
}

__device__ __forceinline__ float2 h2f2(unsigned bits) {
    return __half22float2(*reinterpret_cast<__half2*>(&bits));
}

// ---------------- preprocessing kernels -----------------------------------
__global__ void count_kernel(const int* __restrict__ dst) {
    int i = blockIdx.x * blockDim.x + threadIdx.x;
    if (i < N_EDGES) atomicAdd(&g_cnt[dst[i]], 1);
}

__global__ __launch_bounds__(1024)
void scan1_kernel() {
    __shared__ int sh[1024];
    int b = blockIdx.x, t = threadIdx.x;
    int idx = b * 4096 + t * 4;
    int s = 0;
    if (idx + 3 < N_NODES) {
        int4 v = *(const int4*)&g_cnt[idx];
        s = v.x + v.y + v.z + v.w;
    } else {
        for (int j = 0; j < 4; j++) if (idx + j < N_NODES) s += g_cnt[idx + j];
    }
    sh[t] = s;
    __syncthreads();
    for (int off = 512; off > 0; off >>= 1) {
        if (t < off) sh[t] += sh[t + off];
        __syncthreads();
    }
    if (t == 0) g_bsum[b] = sh[0];
}

__global__ void scan2_kernel(int nblk) {
    if (threadIdx.x == 0) {
        int acc = 0;
        for (int i = 0; i < nblk; i++) { g_boff[i] = acc; acc += g_bsum[i]; }
        g_off[N_NODES] = acc;
    }
}

// scan3 also computes dinv/selfn (folded dinv_kernel)
__global__ __launch_bounds__(1024)
void scan3_kernel() {
    __shared__ int sh[1024];
    int b = blockIdx.x, t = threadIdx.x;
    int idx = b * 4096 + t * 4;
    int c0 = 0, c1 = 0, c2 = 0, c3 = 0;
    if (idx + 3 < N_NODES) {
        int4 v = *(const int4*)&g_cnt[idx];
        c0 = v.x; c1 = v.y; c2 = v.z; c3 = v.w;
    } else {
        if (idx + 0 < N_NODES) c0 = g_cnt[idx + 0];
        if (idx + 1 < N_NODES) c1 = g_cnt[idx + 1];
        if (idx + 2 < N_NODES) c2 = g_cnt[idx + 2];
        if (idx + 3 < N_NODES) c3 = g_cnt[idx + 3];
    }
    int s = c0 + c1 + c2 + c3;
    sh[t] = s;
    __syncthreads();
    for (int off = 1; off < 1024; off <<= 1) {
        int v = (t >= off) ? sh[t - off] : 0;
        __syncthreads();
        sh[t] += v;
        __syncthreads();
    }
    int excl = g_boff[b] + sh[t] - s;
    int4 ov = make_int4(excl, excl + c0, excl + c0 + c1, excl + c0 + c1 + c2);
    int cv[4] = {c0, c1, c2, c3};
    if (idx + 3 < N_NODES) {
        *(int4*)&g_off[idx] = ov;
        *(int4*)&g_cur[idx] = ov;
    } else {
        int o[4] = {ov.x, ov.y, ov.z, ov.w};
        for (int j = 0; j < 4; j++)
            if (idx + j < N_NODES) { g_off[idx + j] = o[j]; g_cur[idx + j] = o[j]; }
    }
    #pragma unroll
    for (int j = 0; j < 4; j++) {
        if (idx + j < N_NODES) {
            float di = rsqrtf((float)cv[j] + 1.0f);
            g_dinv[idx + j]  = di;
            g_selfn[idx + j] = di * di;
        }
    }
}

__global__ void fill_kernel(const int* __restrict__ src, const int* __restrict__ dst) {
    int i = blockIdx.x * blockDim.x + threadIdx.x;
    if (i < N_EDGES) {
        int s = src[i], d = dst[i];
        int pos = atomicAdd(&g_cur[d], 1);
        g_edge[pos] = make_int2(s, __float_as_int(g_dinv[s] * g_dinv[d]));
    }
}

// ---------------- operand packing ------------------------------------------
// converts x -> fp16 AND zeros g_cnt (folded zero_cnt_kernel)
__global__ void convert_x_kernel(const float* __restrict__ x) {
    size_t tidg = (size_t)blockIdx.x * blockDim.x + threadIdx.x;
    if (tidg < N_NODES) g_cnt[tidg] = 0;
    size_t i = tidg * 4;
    if (i >= (size_t)N_NODES * N_FEAT) return;
    float4 v = *(const float4*)(x + i);
    __half2 h01, h23;
    h01.x = __float2half_rn(v.x); h01.y = __float2half_rn(v.y);
    h23.x = __float2half_rn(v.z); h23.y = __float2half_rn(v.w);
    *(uint2*)&g_xh[i] = make_uint2(*(unsigned*)&h01, *(unsigned*)&h23);
}

// B slabs + out_W hi/lo (folded pack_wo_kernel)
__global__ void pack_w_kernel(const float* __restrict__ gcW0,
                              const float* __restrict__ linW0,
                              const float* __restrict__ convsW,
                              const float* __restrict__ linsW,
                              const float* __restrict__ outW) {
    int i = blockIdx.x * blockDim.x + threadIdx.x;
    if (i < 4 * 512 * 512) {
        int l = i >> 18, rem = i & 262143, n = rem >> 9, k = rem & 511;
        int Kl = l ? N_HID : N_FEAT;
        if (k >= Kl) return;
        const float* W;
        if (l == 0) W = (n < 256) ? gcW0 : linW0;
        else        W = ((n < 256) ? convsW : linsW) + (l - 1) * N_HID * N_HID;
        g_B[i] = __float2half_rn(W[k * N_HID + (n & 255)]);
    } else {
        int j = i - 4 * 512 * 512;
        if (j >= 64 * JK_DIM) return;
        int n = j >> 10, k = j & 1023;
        float v = (n < N_CLASS) ? outW[k * N_CLASS + n] : 0.f;
        __half h = __float2half_rn(v);
        g_Woh[j] = h;
        g_Wol[j] = __float2half_rn(v - __half2float(h));
    }
}

// ---------------- fp16 GEMM: C[M,512] = A[M,K] @ B[K,512], 1 MMA/tile ------
// per 32-k chunk buffer: A (10240) + B (10240)
#define SM_ARR 10240
#define SM_BUF 20480

__global__ __launch_bounds__(256)
void gemm_f16_kernel(const __half* __restrict__ Ax,
                     const __half* __restrict__ Bw,
                     __half* __restrict__ Chw, __half* __restrict__ Clin,
                     int M, int K, int lda)
{
    extern __shared__ char smem[];
    const unsigned sbase = su32(smem);
    int tid  = threadIdx.x;
    int lane = tid & 31;
    int wid  = tid >> 5;
    int row0 = blockIdx.y * 128;
    int col0 = blockIdx.x * 128;
    int warpM = (wid >> 2) * 64;
    int warpN = (wid & 3) * 32;

    float acc[4][4][4];
    #pragma unroll
    for (int a = 0; a < 4; a++)
        #pragma unroll
        for (int b = 0; b < 4; b++)
            #pragma unroll
            for (int c = 0; c < 4; c++) acc[a][b][c] = 0.f;

    auto stage = [&](int buf, int k0) {
        #pragma unroll
        for (int t = 0; t < 4; t++) {
            int i = tid + t * 256;
            int arr = i >> 9, rem = i & 511, r = rem >> 2, c = rem & 3;
            unsigned dst = sbase + buf * SM_BUF + arr * SM_ARR + r * 80 + c * 16;
            const __half* src;
            unsigned sz = 16;
            if (arr == 0) {
                int gr = row0 + r;
                if (gr >= M) { gr = M - 1; sz = 0; }
                src = Ax + (size_t)gr * lda + k0 + c * 8;
            } else {
                src = Bw + (size_t)(col0 + r) * 512 + k0 + c * 8;
            }
            cp16(dst, src, sz);
        }
    };

    stage(0, 0);
    CP_COMMIT;

    const int nch = K >> 5;
    for (int ch = 0; ch < nch; ch++) {
        CP_WAIT0;
        __syncthreads();
        if (ch + 1 < nch) {
            stage((ch + 1) & 1, (ch + 1) << 5);
            CP_COMMIT;
        }

        unsigned abase = sbase + (ch & 1) * SM_BUF;
        unsigned bbase = abase + SM_ARR;
        int lrow = lane & 15;
        int lk16 = (lane >> 4) * 16;

        #pragma unroll
        for (int ks = 0; ks < 2; ks++) {
            unsigned aa[4][4];
            #pragma unroll
            for (int mt = 0; mt < 4; mt++) {
                unsigned adr = abase + (warpM + mt * 16 + lrow) * 80 + ks * 32 + lk16;
                LDSM4(aa[mt], adr);
            }
            unsigned bb[2][4];
            #pragma unroll
            for (int g = 0; g < 2; g++) {
                unsigned adr = bbase + (warpN + g * 16 + lrow) * 80 + ks * 32 + lk16;
                LDSM4(bb[g], adr);
            }
            #pragma unroll
            for (int mt = 0; mt < 4; mt++)
                #pragma unroll
                for (int nt = 0; nt < 4; nt++) {
                    int g = nt >> 1, o = nt & 1;
                    mma_f16(acc[mt][nt], aa[mt], bb[g][o], bb[g][2 + o]);
                }
        }
    }

    // epilogue: fp16 store (half2 per acc pair)
    __half* Cg = (col0 < 256) ? Chw : Clin;
    int cb = (col0 < 256) ? col0 : (col0 - 256);
    #pragma unroll
    for (int mt = 0; mt < 4; mt++)
        #pragma unroll
        for (int nt = 0; nt < 4; nt++) {
            int r = row0 + warpM + mt * 16 + (lane >> 2);
            int c = cb + warpN + nt * 8 + (lane & 3) * 2;
            if (r < M) {
                __half2 v; v.x = __float2half_rn(acc[mt][nt][0]);
                           v.y = __float2half_rn(acc[mt][nt][1]);
                *(__half2*)&Cg[(size_t)r * N_HID + c] = v;
            }
            if (r + 8 < M) {
                __half2 v; v.x = __float2half_rn(acc[mt][nt][2]);
                           v.y = __float2half_rn(acc[mt][nt][3]);
                *(__half2*)&Cg[(size_t)(r + 8) * N_HID + c] = v;
            }
        }
}

// ---------------- fused GCN aggregation epilogue ---------------------------
// 32 threads/block, thread owns 8 halfs (uint4 = 16B gathers); fp32 math
__global__ __launch_bounds__(32)
void agg_kernel(const __half* __restrict__ hw, const __half* __restrict__ lin,
                const float* __restrict__ gcb, const float* __restrict__ linb,
                int slot)
{
    int n  = blockIdx.x;
    int f8 = threadIdx.x * 8;
    int beg = g_off[n], end = g_off[n + 1];

    float acc[8];
    #pragma unroll
    for (int j = 0; j < 8; j++) acc[j] = 0.f;

    int e = beg;
    for (; e + 3 < end; e += 4) {
        int2 p0 = g_edge[e],     p1 = g_edge[e + 1];
        int2 p2 = g_edge[e + 2], p3 = g_edge[e + 3];
        uint4 v0 = *(const uint4*)&hw[(size_t)p0.x * N_HID + f8];
        uint4 v1 = *(const uint4*)&hw[(size_t)p1.x * N_HID + f8];
        uint4 v2 = *(const uint4*)&hw[(size_t)p2.x * N_HID + f8];
        uint4 v3 = *(const uint4*)&hw[(size_t)p3.x * N_HID + f8];
        float c0 = __int_as_float(p0.y), c1 = __int_as_float(p1.y);
        float c2 = __int_as_float(p2.y), c3 = __int_as_float(p3.y);
        const unsigned* w0 = &v0.x; const unsigned* w1 = &v1.x;
        const unsigned* w2 = &v2.x; const unsigned* w3 = &v3.x;
        #pragma unroll
        for (int j = 0; j < 4; j++) {
            float2 f0 = h2f2(w0[j]), f1 = h2f2(w1[j]);
            float2 f2 = h2f2(w2[j]), f3 = h2f2(w3[j]);
            acc[2*j]   += c0 * f0.x + c1 * f1.x + c2 * f2.x + c3 * f3.x;
            acc[2*j+1] += c0 * f0.y + c1 * f1.y + c2 * f2.y + c3 * f3.y;
        }
    }
    for (; e < end; e++) {
        int2 p = g_edge[e];
        uint4 v = *(const uint4*)&hw[(size_t)p.x * N_HID + f8];
        float c = __int_as_float(p.y);
        const unsigned* w = &v.x;
        #pragma unroll
        for (int j = 0; j < 4; j++) {
            float2 f = h2f2(w[j]);
            acc[2*j]   += c * f.x;
            acc[2*j+1] += c * f.y;
        }
    }

    float sn = g_selfn[n];
    uint4 vs = *(const uint4*)&hw [(size_t)n * N_HID + f8];
    uint4 vl = *(const uint4*)&lin[(size_t)n * N_HID + f8];
    float4 bg0 = *(const float4*)&gcb[f8];
    float4 bg1 = *(const float4*)&gcb[f8 + 4];
    float4 bl0 = *(const float4*)&linb[f8];
    float4 bl1 = *(const float4*)&linb[f8 + 4];
    float bgv[8] = {bg0.x, bg0.y, bg0.z, bg0.w, bg1.x, bg1.y, bg1.z, bg1.w};
    float blv[8] = {bl0.x, bl0.y, bl0.z, bl0.w, bl1.x, bl1.y, bl1.z, bl1.w};

    const unsigned* ws = &vs.x;
    const unsigned* wl = &vl.x;
    unsigned hh[4], ll[4];
    #pragma unroll
    for (int j = 0; j < 4; j++) {
        float2 fs = h2f2(ws[j]);
        float2 fl = h2f2(wl[j]);
        float r0 = fmaxf(acc[2*j]   + sn * fs.x + bgv[2*j]   + fl.x + blv[2*j],   0.f);
        float r1 = fmaxf(acc[2*j+1] + sn * fs.y + bgv[2*j+1] + fl.y + blv[2*j+1], 0.f);
        hh[j] = split_pack_h(r0, r1, ll[j]);
    }
    size_t o = (size_t)n * JK_DIM + slot * N_HID + f8;
    *(uint4*)&g_jkh[o] = make_uint4(hh[0], hh[1], hh[2], hh[3]);
    *(uint4*)&g_jkl[o] = make_uint4(ll[0], ll[1], ll[2], ll[3]);
}

// ---------------- output GEMM (fp16 3-term, negligible error) --------------
#define OSM_A  10240
#define OSM_B  5120
#define OSM_BUF (2 * OSM_A + 2 * OSM_B)   // 30720

__global__ __launch_bounds__(256)
void out_mma_kernel(const float* __restrict__ bias, float* __restrict__ out)
{
    extern __shared__ char smem[];
    const unsigned sbase = su32(smem);
    int tid  = threadIdx.x;
    int lane = tid & 31;
    int wid  = tid >> 5;
    int row0 = blockIdx.x * 128;

    float acc[5][4];
    #pragma unroll
    for (int a = 0; a < 5; a++)
        #pragma unroll
        for (int c = 0; c < 4; c++) acc[a][c] = 0.f;

    auto stage = [&](int buf, int k0) {
        #pragma unroll
        for (int t = 0; t < 6; t++) {
            int i = tid + t * 256;
            unsigned dst; const __half* src; unsigned sz = 16;
            if (i < 1024) {
                int hl = i >> 9, rem = i & 511, r = rem >> 2, c = rem & 3;
                int gr = row0 + r;
                if (gr >= N_NODES) { gr = N_NODES - 1; sz = 0; }
                src = (hl ? g_jkl : g_jkh) + (size_t)gr * JK_DIM + k0 + c * 8;
                dst = sbase + buf * OSM_BUF + hl * OSM_A + r * 80 + c * 16;
            } else {
                int j = i - 1024;
                int hl = j >> 8, rem = j & 255, r = rem >> 2, c = rem & 3;
                src = (hl ? g_Wol : g_Woh) + (size_t)r * JK_DIM + k0 + c * 8;
                dst = sbase + buf * OSM_BUF + 2 * OSM_A + hl * OSM_B + r * 80 + c * 16;
            }
            cp16(dst, src, sz);
        }
    };

    stage(0, 0);
    CP_COMMIT;

    const int nch = JK_DIM / 32;
    for (int ch = 0; ch < nch; ch++) {
        CP_WAIT0;
        __syncthreads();
        if (ch + 1 < nch) {
            stage((ch + 1) & 1, (ch + 1) * 32);
            CP_COMMIT;
        }

        unsigned abase = sbase + (ch & 1) * OSM_BUF;
        unsigned bbase = abase + 2 * OSM_A;
        int lrow = lane & 15;
        int lk16 = (lane >> 4) * 16;

        #pragma unroll
        for (int ks = 0; ks < 2; ks++) {
            unsigned ah[4], al[4];
            unsigned adr = abase + (wid * 16 + lrow) * 80 + ks * 32 + lk16;
            LDSM4(ah, adr);
            LDSM4(al, adr + OSM_A);
            unsigned bh[3][4], bl[3][4];
            #pragma unroll
            for (int g = 0; g < 3; g++) {
                unsigned badr = bbase + (g * 16 + lrow) * 80 + ks * 32 + lk16;
                LDSM4(bh[g], badr);
                LDSM4(bl[g], badr + OSM_B);
            }
            #pragma unroll
            for (int nt = 0; nt < 5; nt++) {
                int g = nt >> 1, o = nt & 1;
                mma_f16(acc[nt], ah, bh[g][o], bh[g][2 + o]);
            }
            #pragma unroll
            for (int nt = 0; nt < 5; nt++) {
                int g = nt >> 1, o = nt & 1;
                mma_f16(acc[nt], ah, bl[g][o], bl[g][2 + o]);
            }
            #pragma unroll
            for (int nt = 0; nt < 5; nt++) {
                int g = nt >> 1, o = nt & 1;
                mma_f16(acc[nt], al, bh[g][o], bh[g][2 + o]);
            }
        }
    }

    #pragma unroll
    for (int nt = 0; nt < 5; nt++) {
        int c = nt * 8 + (lane & 3) * 2;
        float2 bv = make_float2(bias[c], bias[c + 1]);
        int r = row0 + wid * 16 + (lane >> 2);
        if (r < N_NODES)
            *(float2*)&out[(size_t)r * N_CLASS + c] =
                make_float2(acc[nt][0] + bv.x, acc[nt][1] + bv.y);
        if (r + 8 < N_NODES)
            *(float2*)&out[(size_t)(r + 8) * N_CLASS + c] =
                make_float2(acc[nt][2] + bv.x, acc[nt][3] + bv.y);
    }
}

// ---------------- launch ---------------------------------------------------
extern "C" void kernel_launch(void* const* d_in, const int* in_sizes, int n_in,
                              void* d_out, int out_size)
{
    const float* x        = (const float*)d_in[0];
    const int*   edge     = (const int*)  d_in[1];
    const float* in_gc_W  = (const float*)d_in[2];
    const float* in_gc_b  = (const float*)d_in[3];
    const float* in_lin_W = (const float*)d_in[4];
    const float* in_lin_b = (const float*)d_in[5];
    const float* convs_W  = (const float*)d_in[6];
    const float* convs_b  = (const float*)d_in[7];
    const float* lins_W   = (const float*)d_in[8];
    const float* lins_b   = (const float*)d_in[9];
    const float* out_W    = (const float*)d_in[10];
    const float* out_b    = (const float*)d_in[11];
    float*       out      = (float*)d_out;

    const int* src = edge;
    const int* dst = edge + N_EDGES;

    __half *p_hw, *p_lin, *p_xh, *p_jkh, *p_jkl, *p_B;
    cudaGetSymbolAddress((void**)&p_hw,  g_hw);
    cudaGetSymbolAddress((void**)&p_lin, g_lin);
    cudaGetSymbolAddress((void**)&p_xh,  g_xh);
    cudaGetSymbolAddress((void**)&p_jkh, g_jkh);
    cudaGetSymbolAddress((void**)&p_jkl, g_jkl);
    cudaGetSymbolAddress((void**)&p_B,   g_B);

    cudaFuncSetAttribute(gemm_f16_kernel,
                         cudaFuncAttributeMaxDynamicSharedMemorySize, 2 * SM_BUF);
    cudaFuncSetAttribute(out_mma_kernel,
                         cudaFuncAttributeMaxDynamicSharedMemorySize, 2 * OSM_BUF);

    dim3 ggrid(4, (N_NODES + 127) / 128);

    // order: my #4 (profiled under ncu -s 5) = gemm layer 0
    convert_x_kernel<<<(N_NODES * N_FEAT / 4 + 255) / 256, 256>>>(x);  // + zero cnt
    pack_w_kernel<<<(4 * 512 * 512 + 64 * JK_DIM + 255) / 256, 256>>>(
        in_gc_W, in_lin_W, convs_W, lins_W, out_W);                    // + pack Wo
    count_kernel<<<(N_EDGES + 255) / 256, 256>>>(dst);
    gemm_f16_kernel<<<ggrid, 256, 2 * SM_BUF>>>(      // <- profiled
        p_xh, p_B, p_hw, p_lin, N_NODES, N_FEAT, N_FEAT);
    scan1_kernel<<<13, 1024>>>();
    scan2_kernel<<<1, 32>>>(13);
    scan3_kernel<<<13, 1024>>>();                      // + dinv/selfn
    fill_kernel<<<(N_EDGES + 255) / 256, 256>>>(src, dst);

    agg_kernel<<<N_NODES, 32>>>(p_hw, p_lin, in_gc_b, in_lin_b, 0);

    for (int i = 0; i < N_LAYER - 1; i++) {
        gemm_f16_kernel<<<ggrid, 256, 2 * SM_BUF>>>(
            p_jkh + i * N_HID, p_B + (size_t)(i + 1) * 512 * 512,
            p_hw, p_lin, N_NODES, N_HID, JK_DIM);
        agg_kernel<<<N_NODES, 32>>>(p_hw, p_lin,
                                    convs_b + i * N_HID, lins_b + i * N_HID,
                                    i + 1);
    }

    out_mma_kernel<<<(N_NODES + 127) / 128, 256, 2 * OSM_BUF>>>(out_b, out);
}

// round 13
// speedup vs baseline: 1.5288x; 1.1793x over previous
#include <cuda_runtime.h>
#include <cuda_fp16.h>

#define N_NODES 50000
#define N_EDGES 800000
#define N_FEAT  512
#define N_HID   256
#define N_LAYER 4
#define N_CLASS 40
#define JK_DIM  (N_HID * N_LAYER)   // 1024

// ---------------- scratch (device globals; no allocation allowed) ----------
__device__ int   g_cnt[N_NODES];
__device__ int   g_off[N_NODES + 1];
__device__ int   g_cur[N_NODES];
__device__ int   g_bsum[16];
__device__ int   g_boff[16];
__device__ __align__(16) int2 g_edge[N_EDGES];      // {src, coef bits}
__device__ float g_dinv[N_NODES];
__device__ float g_selfn[N_NODES];
// GEMM outputs stored fp16; aggregation math is fp32
__device__ __align__(256) __half g_hw [N_NODES * N_HID];           // 25.6 MB
__device__ __align__(256) __half g_lin[N_NODES * N_HID];           // 25.6 MB
// jk slab fp16 (single precision level everywhere now)
__device__ __align__(256) __half g_jkh[(size_t)N_NODES * JK_DIM];
__device__ __align__(256) __half g_xh[(size_t)N_NODES * N_FEAT];
// weights: single fp16; layer l n-major [512n][512k] at l*512*512
__device__ __align__(256) __half g_B[4 * 512 * 512];
__device__ __align__(256) __half g_Woh[64 * JK_DIM];

// ---------------- helpers ---------------------------------------------------
__device__ __forceinline__ unsigned su32(const void* p) {
    unsigned a;
    asm("{ .reg .u64 t; cvta.to.shared.u64 t, %1; cvt.u32.u64 %0, t; }"
        : "=r"(a) : "l"(p));
    return a;
}

__device__ __forceinline__ void cp16(unsigned d, const void* s, unsigned sz) {
    asm volatile("cp.async.cg.shared.global [%0], [%1], 16, %2;"
                 :: "r"(d), "l"(s), "r"(sz) : "memory");
}
#define CP_COMMIT asm volatile("cp.async.commit_group;" ::: "memory")
#define CP_WAIT0  asm volatile("cp.async.wait_group 0;" ::: "memory")

#define LDSM4(r, a) \
    asm volatile("ldmatrix.sync.aligned.m8n8.x4.shared.b16 {%0,%1,%2,%3}, [%4];" \
        : "=r"((r)[0]), "=r"((r)[1]), "=r"((r)[2]), "=r"((r)[3]) : "r"(a))

__device__ __forceinline__ void mma_f16(float* c, const unsigned* a,
                                        unsigned b0, unsigned b1) {
    asm volatile("mma.sync.aligned.m16n8k16.row.col.f32.f16.f16.f32 "
        "{%0,%1,%2,%3}, {%4,%5,%6,%7}, {%8,%9}, {%0,%1,%2,%3};"
        : "+f"(c[0]), "+f"(c[1]), "+f"(c[2]), "+f"(c[3])
        : "r"(a[0]), "r"(a[1]), "r"(a[2]), "r"(a[3]), "r"(b0), "r"(b1));
}

__device__ __forceinline__ float2 h2f2(unsigned bits) {
    return __half22float2(*reinterpret_cast<__half2*>(&bits));
}

__device__ __forceinline__ unsigned pack_h2(float a, float b) {
    __half2 h;
    h.x = __float2half_rn(a);
    h.y = __float2half_rn(b);
    return *reinterpret_cast<unsigned*>(&h);
}

// ---------------- preprocessing kernels -----------------------------------
__global__ void count_kernel(const int* __restrict__ dst) {
    int i = blockIdx.x * blockDim.x + threadIdx.x;
    if (i < N_EDGES) atomicAdd(&g_cnt[dst[i]], 1);
}

__global__ __launch_bounds__(1024)
void scan1_kernel() {
    __shared__ int sh[1024];
    int b = blockIdx.x, t = threadIdx.x;
    int idx = b * 4096 + t * 4;
    int s = 0;
    if (idx + 3 < N_NODES) {
        int4 v = *(const int4*)&g_cnt[idx];
        s = v.x + v.y + v.z + v.w;
    } else {
        for (int j = 0; j < 4; j++) if (idx + j < N_NODES) s += g_cnt[idx + j];
    }
    sh[t] = s;
    __syncthreads();
    for (int off = 512; off > 0; off >>= 1) {
        if (t < off) sh[t] += sh[t + off];
        __syncthreads();
    }
    if (t == 0) g_bsum[b] = sh[0];
}

__global__ void scan2_kernel(int nblk) {
    if (threadIdx.x == 0) {
        int acc = 0;
        for (int i = 0; i < nblk; i++) { g_boff[i] = acc; acc += g_bsum[i]; }
        g_off[N_NODES] = acc;
    }
}

// scan3 also computes dinv/selfn
__global__ __launch_bounds__(1024)
void scan3_kernel() {
    __shared__ int sh[1024];
    int b = blockIdx.x, t = threadIdx.x;
    int idx = b * 4096 + t * 4;
    int c0 = 0, c1 = 0, c2 = 0, c3 = 0;
    if (idx + 3 < N_NODES) {
        int4 v = *(const int4*)&g_cnt[idx];
        c0 = v.x; c1 = v.y; c2 = v.z; c3 = v.w;
    } else {
        if (idx + 0 < N_NODES) c0 = g_cnt[idx + 0];
        if (idx + 1 < N_NODES) c1 = g_cnt[idx + 1];
        if (idx + 2 < N_NODES) c2 = g_cnt[idx + 2];
        if (idx + 3 < N_NODES) c3 = g_cnt[idx + 3];
    }
    int s = c0 + c1 + c2 + c3;
    sh[t] = s;
    __syncthreads();
    for (int off = 1; off < 1024; off <<= 1) {
        int v = (t >= off) ? sh[t - off] : 0;
        __syncthreads();
        sh[t] += v;
        __syncthreads();
    }
    int excl = g_boff[b] + sh[t] - s;
    int4 ov = make_int4(excl, excl + c0, excl + c0 + c1, excl + c0 + c1 + c2);
    int cv[4] = {c0, c1, c2, c3};
    if (idx + 3 < N_NODES) {
        *(int4*)&g_off[idx] = ov;
        *(int4*)&g_cur[idx] = ov;
    } else {
        int o[4] = {ov.x, ov.y, ov.z, ov.w};
        for (int j = 0; j < 4; j++)
            if (idx + j < N_NODES) { g_off[idx + j] = o[j]; g_cur[idx + j] = o[j]; }
    }
    #pragma unroll
    for (int j = 0; j < 4; j++) {
        if (idx + j < N_NODES) {
            float di = rsqrtf((float)cv[j] + 1.0f);
            g_dinv[idx + j]  = di;
            g_selfn[idx + j] = di * di;
        }
    }
}

__global__ void fill_kernel(const int* __restrict__ src, const int* __restrict__ dst) {
    int i = blockIdx.x * blockDim.x + threadIdx.x;
    if (i < N_EDGES) {
        int s = src[i], d = dst[i];
        int pos = atomicAdd(&g_cur[d], 1);
        g_edge[pos] = make_int2(s, __float_as_int(g_dinv[s] * g_dinv[d]));
    }
}

// ---------------- operand packing ------------------------------------------
// converts x -> fp16 AND zeros g_cnt
__global__ void convert_x_kernel(const float* __restrict__ x) {
    size_t tidg = (size_t)blockIdx.x * blockDim.x + threadIdx.x;
    if (tidg < N_NODES) g_cnt[tidg] = 0;
    size_t i = tidg * 4;
    if (i >= (size_t)N_NODES * N_FEAT) return;
    float4 v = *(const float4*)(x + i);
    *(uint2*)&g_xh[i] = make_uint2(pack_h2(v.x, v.y), pack_h2(v.z, v.w));
}

// B slabs + out_W
__global__ void pack_w_kernel(const float* __restrict__ gcW0,
                              const float* __restrict__ linW0,
                              const float* __restrict__ convsW,
                              const float* __restrict__ linsW,
                              const float* __restrict__ outW) {
    int i = blockIdx.x * blockDim.x + threadIdx.x;
    if (i < 4 * 512 * 512) {
        int l = i >> 18, rem = i & 262143, n = rem >> 9, k = rem & 511;
        int Kl = l ? N_HID : N_FEAT;
        if (k >= Kl) return;
        const float* W;
        if (l == 0) W = (n < 256) ? gcW0 : linW0;
        else        W = ((n < 256) ? convsW : linsW) + (l - 1) * N_HID * N_HID;
        g_B[i] = __float2half_rn(W[k * N_HID + (n & 255)]);
    } else {
        int j = i - 4 * 512 * 512;
        if (j >= 64 * JK_DIM) return;
        int n = j >> 10, k = j & 1023;
        g_Woh[j] = __float2half_rn((n < N_CLASS) ? outW[k * N_CLASS + n] : 0.f);
    }
}

// ---------------- fp16 GEMM: C[M,512] = A[M,K] @ B[K,512], K-chunk 64 ------
// per-chunk buffer: A (128 rows x 144B) + B (128 rows x 144B); rows = 128B
// data + 16B pad (stride 36 words ≡ 4 mod 32 -> conflict-free LDSM phases)
#define SM_ARR 18432
#define SM_BUF 36864

__global__ __launch_bounds__(256)
void gemm_f16_kernel(const __half* __restrict__ Ax,
                     const __half* __restrict__ Bw,
                     __half* __restrict__ Chw, __half* __restrict__ Clin,
                     int M, int K, int lda)
{
    extern __shared__ char smem[];
    const unsigned sbase = su32(smem);
    int tid  = threadIdx.x;
    int lane = tid & 31;
    int wid  = tid >> 5;
    int row0 = blockIdx.y * 128;
    int col0 = blockIdx.x * 128;
    int warpM = (wid >> 2) * 64;
    int warpN = (wid & 3) * 32;

    float acc[4][4][4];
    #pragma unroll
    for (int a = 0; a < 4; a++)
        #pragma unroll
        for (int b = 0; b < 4; b++)
            #pragma unroll
            for (int c = 0; c < 4; c++) acc[a][b][c] = 0.f;

    auto stage = [&](int buf, int k0) {
        #pragma unroll
        for (int t = 0; t < 8; t++) {
            int i = tid + t * 256;          // 0..2047
            int arr = i >> 10, rem = i & 1023, r = rem >> 3, c = rem & 7;
            unsigned dst = sbase + buf * SM_BUF + arr * SM_ARR + r * 144 + c * 16;
            const __half* src;
            unsigned sz = 16;
            if (arr == 0) {
                int gr = row0 + r;
                if (gr >= M) { gr = M - 1; sz = 0; }
                src = Ax + (size_t)gr * lda + k0 + c * 8;
            } else {
                src = Bw + (size_t)(col0 + r) * 512 + k0 + c * 8;
            }
            cp16(dst, src, sz);
        }
    };

    stage(0, 0);
    CP_COMMIT;

    const int nch = K >> 6;
    for (int ch = 0; ch < nch; ch++) {
        CP_WAIT0;
        __syncthreads();
        if (ch + 1 < nch) {
            stage((ch + 1) & 1, (ch + 1) << 6);
            CP_COMMIT;
        }

        unsigned abase = sbase + (ch & 1) * SM_BUF;
        unsigned bbase = abase + SM_ARR;
        int lrow = lane & 15;
        int lk16 = (lane >> 4) * 16;

        #pragma unroll
        for (int ks = 0; ks < 4; ks++) {
            unsigned aa[4][4];
            #pragma unroll
            for (int mt = 0; mt < 4; mt++) {
                unsigned adr = abase + (warpM + mt * 16 + lrow) * 144 + ks * 32 + lk16;
                LDSM4(aa[mt], adr);
            }
            unsigned bb[2][4];
            #pragma unroll
            for (int g = 0; g < 2; g++) {
                unsigned adr = bbase + (warpN + g * 16 + lrow) * 144 + ks * 32 + lk16;
                LDSM4(bb[g], adr);
            }
            #pragma unroll
            for (int mt = 0; mt < 4; mt++)
                #pragma unroll
                for (int nt = 0; nt < 4; nt++) {
                    int g = nt >> 1, o = nt & 1;
                    mma_f16(acc[mt][nt], aa[mt], bb[g][o], bb[g][2 + o]);
                }
        }
    }

    __half* Cg = (col0 < 256) ? Chw : Clin;
    int cb = (col0 < 256) ? col0 : (col0 - 256);
    #pragma unroll
    for (int mt = 0; mt < 4; mt++)
        #pragma unroll
        for (int nt = 0; nt < 4; nt++) {
            int r = row0 + warpM + mt * 16 + (lane >> 2);
            int c = cb + warpN + nt * 8 + (lane & 3) * 2;
            if (r < M)
                *(__half2*)&Cg[(size_t)r * N_HID + c] =
                    *(__half2*)&(unsigned&)(*(unsigned[]){pack_h2(acc[mt][nt][0], acc[mt][nt][1])});
            if (r + 8 < M)
                *(__half2*)&Cg[(size_t)(r + 8) * N_HID + c] =
                    *(__half2*)&(unsigned&)(*(unsigned[]){pack_h2(acc[mt][nt][2], acc[mt][nt][3])});
        }
}

// ---------------- fused GCN aggregation epilogue ---------------------------
__global__ __launch_bounds__(32)
void agg_kernel(const __half* __restrict__ hw, const __half* __restrict__ lin,
                const float* __restrict__ gcb, const float* __restrict__ linb,
                int slot)
{
    int n  = blockIdx.x;
    int f8 = threadIdx.x * 8;
    int beg = g_off[n], end = g_off[n + 1];

    float acc[8];
    #pragma unroll
    for (int j = 0; j < 8; j++) acc[j] = 0.f;

    int e = beg;
    for (; e + 3 < end; e += 4) {
        int2 p0 = g_edge[e],     p1 = g_edge[e + 1];
        int2 p2 = g_edge[e + 2], p3 = g_edge[e + 3];
        uint4 v0 = *(const uint4*)&hw[(size_t)p0.x * N_HID + f8];
        uint4 v1 = *(const uint4*)&hw[(size_t)p1.x * N_HID + f8];
        uint4 v2 = *(const uint4*)&hw[(size_t)p2.x * N_HID + f8];
        uint4 v3 = *(const uint4*)&hw[(size_t)p3.x * N_HID + f8];
        float c0 = __int_as_float(p0.y), c1 = __int_as_float(p1.y);
        float c2 = __int_as_float(p2.y), c3 = __int_as_float(p3.y);
        const unsigned* w0 = &v0.x; const unsigned* w1 = &v1.x;
        const unsigned* w2 = &v2.x; const unsigned* w3 = &v3.x;
        #pragma unroll
        for (int j = 0; j < 4; j++) {
            float2 f0 = h2f2(w0[j]), f1 = h2f2(w1[j]);
            float2 f2 = h2f2(w2[j]), f3 = h2f2(w3[j]);
            acc[2*j]   += c0 * f0.x + c1 * f1.x + c2 * f2.x + c3 * f3.x;
            acc[2*j+1] += c0 * f0.y + c1 * f1.y + c2 * f2.y + c3 * f3.y;
        }
    }
    for (; e < end; e++) {
        int2 p = g_edge[e];
        uint4 v = *(const uint4*)&hw[(size_t)p.x * N_HID + f8];
        float c = __int_as_float(p.y);
        const unsigned* w = &v.x;
        #pragma unroll
        for (int j = 0; j < 4; j++) {
            float2 f = h2f2(w[j]);
            acc[2*j]   += c * f.x;
            acc[2*j+1] += c * f.y;
        }
    }

    float sn = g_selfn[n];
    uint4 vs = *(const uint4*)&hw [(size_t)n * N_HID + f8];
    uint4 vl = *(const uint4*)&lin[(size_t)n * N_HID + f8];
    float4 bg0 = *(const float4*)&gcb[f8];
    float4 bg1 = *(const float4*)&gcb[f8 + 4];
    float4 bl0 = *(const float4*)&linb[f8];
    float4 bl1 = *(const float4*)&linb[f8 + 4];
    float bgv[8] = {bg0.x, bg0.y, bg0.z, bg0.w, bg1.x, bg1.y, bg1.z, bg1.w};
    float blv[8] = {bl0.x, bl0.y, bl0.z, bl0.w, bl1.x, bl1.y, bl1.z, bl1.w};

    const unsigned* ws = &vs.x;
    const unsigned* wl = &vl.x;
    unsigned hh[4];
    #pragma unroll
    for (int j = 0; j < 4; j++) {
        float2 fs = h2f2(ws[j]);
        float2 fl = h2f2(wl[j]);
        float r0 = fmaxf(acc[2*j]   + sn * fs.x + bgv[2*j]   + fl.x + blv[2*j],   0.f);
        float r1 = fmaxf(acc[2*j+1] + sn * fs.y + bgv[2*j+1] + fl.y + blv[2*j+1], 0.f);
        hh[j] = pack_h2(r0, r1);
    }
    size_t o = (size_t)n * JK_DIM + slot * N_HID + f8;
    *(uint4*)&g_jkh[o] = make_uint4(hh[0], hh[1], hh[2], hh[3]);
}

// ---------------- output GEMM (single-term fp16) ---------------------------
#define OSM_A  10240
#define OSM_B  5120
#define OSM_BUF (OSM_A + OSM_B)   // 15360

__global__ __launch_bounds__(256)
void out_mma_kernel(const float* __restrict__ bias, float* __restrict__ out)
{
    extern __shared__ char smem[];
    const unsigned sbase = su32(smem);
    int tid  = threadIdx.x;
    int lane = tid & 31;
    int wid  = tid >> 5;
    int row0 = blockIdx.x * 128;

    float acc[5][4];
    #pragma unroll
    for (int a = 0; a < 5; a++)
        #pragma unroll
        for (int c = 0; c < 4; c++) acc[a][c] = 0.f;

    auto stage = [&](int buf, int k0) {
        #pragma unroll
        for (int t = 0; t < 3; t++) {
            int i = tid + t * 256;          // 0..767
            unsigned dst; const __half* src; unsigned sz = 16;
            if (i < 512) {
                int r = i >> 2, c = i & 3;
                int gr = row0 + r;
                if (gr >= N_NODES) { gr = N_NODES - 1; sz = 0; }
                src = g_jkh + (size_t)gr * JK_DIM + k0 + c * 8;
                dst = sbase + buf * OSM_BUF + r * 80 + c * 16;
            } else {
                int j = i - 512;
                int r = j >> 2, c = j & 3;
                src = g_Woh + (size_t)r * JK_DIM + k0 + c * 8;
                dst = sbase + buf * OSM_BUF + OSM_A + r * 80 + c * 16;
            }
            cp16(dst, src, sz);
        }
    };

    stage(0, 0);
    CP_COMMIT;

    const int nch = JK_DIM / 32;
    for (int ch = 0; ch < nch; ch++) {
        CP_WAIT0;
        __syncthreads();
        if (ch + 1 < nch) {
            stage((ch + 1) & 1, (ch + 1) * 32);
            CP_COMMIT;
        }

        unsigned abase = sbase + (ch & 1) * OSM_BUF;
        unsigned bbase = abase + OSM_A;
        int lrow = lane & 15;
        int lk16 = (lane >> 4) * 16;

        #pragma unroll
        for (int ks = 0; ks < 2; ks++) {
            unsigned ah[4];
            unsigned adr = abase + (wid * 16 + lrow) * 80 + ks * 32 + lk16;
            LDSM4(ah, adr);
            unsigned bh[3][4];
            #pragma unroll
            for (int g = 0; g < 3; g++) {
                unsigned badr = bbase + (g * 16 + lrow) * 80 + ks * 32 + lk16;
                LDSM4(bh[g], badr);
            }
            #pragma unroll
            for (int nt = 0; nt < 5; nt++) {
                int g = nt >> 1, o = nt & 1;
                mma_f16(acc[nt], ah, bh[g][o], bh[g][2 + o]);
            }
        }
    }

    #pragma unroll
    for (int nt = 0; nt < 5; nt++) {
        int c = nt * 8 + (lane & 3) * 2;
        float2 bv = make_float2(bias[c], bias[c + 1]);
        int r = row0 + wid * 16 + (lane >> 2);
        if (r < N_NODES)
            *(float2*)&out[(size_t)r * N_CLASS + c] =
                make_float2(acc[nt][0] + bv.x, acc[nt][1] + bv.y);
        if (r + 8 < N_NODES)
            *(float2*)&out[(size_t)(r + 8) * N_CLASS + c] =
                make_float2(acc[nt][2] + bv.x, acc[nt][3] + bv.y);
    }
}

// ---------------- launch ---------------------------------------------------
extern "C" void kernel_launch(void* const* d_in, const int* in_sizes, int n_in,
                              void* d_out, int out_size)
{
    const float* x        = (const float*)d_in[0];
    const int*   edge     = (const int*)  d_in[1];
    const float* in_gc_W  = (const float*)d_in[2];
    const float* in_gc_b  = (const float*)d_in[3];
    const float* in_lin_W = (const float*)d_in[4];
    const float* in_lin_b = (const float*)d_in[5];
    const float* convs_W  = (const float*)d_in[6];
    const float* convs_b  = (const float*)d_in[7];
    const float* lins_W   = (const float*)d_in[8];
    const float* lins_b   = (const float*)d_in[9];
    const float* out_W    = (const float*)d_in[10];
    const float* out_b    = (const float*)d_in[11];
    float*       out      = (float*)d_out;

    const int* src = edge;
    const int* dst = edge + N_EDGES;

    __half *p_hw, *p_lin, *p_xh, *p_jkh, *p_B;
    cudaGetSymbolAddress((void**)&p_hw,  g_hw);
    cudaGetSymbolAddress((void**)&p_lin, g_lin);
    cudaGetSymbolAddress((void**)&p_xh,  g_xh);
    cudaGetSymbolAddress((void**)&p_jkh, g_jkh);
    cudaGetSymbolAddress((void**)&p_B,   g_B);

    cudaFuncSetAttribute(gemm_f16_kernel,
                         cudaFuncAttributeMaxDynamicSharedMemorySize, 2 * SM_BUF);
    cudaFuncSetAttribute(out_mma_kernel,
                         cudaFuncAttributeMaxDynamicSharedMemorySize, 2 * OSM_BUF);

    dim3 ggrid(4, (N_NODES + 127) / 128);

    // order: my #4 (profiled under ncu -s 5) = gemm layer 0
    convert_x_kernel<<<(N_NODES * N_FEAT / 4 + 255) / 256, 256>>>(x);
    pack_w_kernel<<<(4 * 512 * 512 + 64 * JK_DIM + 255) / 256, 256>>>(
        in_gc_W, in_lin_W, convs_W, lins_W, out_W);
    count_kernel<<<(N_EDGES + 255) / 256, 256>>>(dst);
    gemm_f16_kernel<<<ggrid, 256, 2 * SM_BUF>>>(      // <- profiled
        p_xh, p_B, p_hw, p_lin, N_NODES, N_FEAT, N_FEAT);
    scan1_kernel<<<13, 1024>>>();
    scan2_kernel<<<1, 32>>>(13);
    scan3_kernel<<<13, 1024>>>();
    fill_kernel<<<(N_EDGES + 255) / 256, 256>>>(src, dst);

    agg_kernel<<<N_NODES, 32>>>(p_hw, p_lin, in_gc_b, in_lin_b, 0);

    for (int i = 0; i < N_LAYER - 1; i++) {
        gemm_f16_kernel<<<ggrid, 256, 2 * SM_BUF>>>(
            p_jkh + i * N_HID, p_B + (size_t)(i + 1) * 512 * 512,
            p_hw, p_lin, N_NODES, N_HID, JK_DIM);
        agg_kernel<<<N_NODES, 32>>>(p_hw, p_lin,
                                    convs_b + i * N_HID, lins_b + i * N_HID,
                                    i + 1);
    }

    out_mma_kernel<<<(N_NODES + 127) / 128, 256, 2 * OSM_BUF>>>(out_b, out);
}

// round 14
// speedup vs baseline: 1.5716x; 1.0280x over previous
#include <cuda_runtime.h>
#include <cuda_fp16.h>

#define N_NODES 50000
#define N_EDGES 800000
#define N_FEAT  512
#define N_HID   256
#define N_LAYER 4
#define N_CLASS 40
#define JK_DIM  (N_HID * N_LAYER)   // 1024

// ---------------- scratch (device globals; no allocation allowed) ----------
__device__ int   g_cnt[N_NODES];
__device__ int   g_off[N_NODES + 1];
__device__ int   g_cur[N_NODES];
__device__ int   g_bsum[16];
__device__ int   g_boff[16];
__device__ __align__(16) int2 g_edge[N_EDGES];      // {src, coef bits}
__device__ float g_dinv[N_NODES];
__device__ float g_selfn[N_NODES];
__device__ __align__(256) __half g_hw [N_NODES * N_HID];
__device__ __align__(256) __half g_lin[N_NODES * N_HID];
__device__ __align__(256) __half g_jkh[(size_t)N_NODES * JK_DIM];
__device__ __align__(256) __half g_xh[(size_t)N_NODES * N_FEAT];
__device__ __align__(256) __half g_B[4 * 512 * 512];
__device__ __align__(256) __half g_Woh[64 * JK_DIM];

// ---------------- helpers ---------------------------------------------------
__device__ __forceinline__ unsigned su32(const void* p) {
    unsigned a;
    asm("{ .reg .u64 t; cvta.to.shared.u64 t, %1; cvt.u32.u64 %0, t; }"
        : "=r"(a) : "l"(p));
    return a;
}

__device__ __forceinline__ void cp16(unsigned d, const void* s, unsigned sz) {
    asm volatile("cp.async.cg.shared.global [%0], [%1], 16, %2;"
                 :: "r"(d), "l"(s), "r"(sz) : "memory");
}
#define CP_COMMIT asm volatile("cp.async.commit_group;" ::: "memory")
#define CP_WAIT0  asm volatile("cp.async.wait_group 0;" ::: "memory")

#define LDSM4(r, a) \
    asm volatile("ldmatrix.sync.aligned.m8n8.x4.shared.b16 {%0,%1,%2,%3}, [%4];" \
        : "=r"((r)[0]), "=r"((r)[1]), "=r"((r)[2]), "=r"((r)[3]) : "r"(a))

__device__ __forceinline__ void mma_f16(float* c, const unsigned* a,
                                        unsigned b0, unsigned b1) {
    asm volatile("mma.sync.aligned.m16n8k16.row.col.f32.f16.f16.f32 "
        "{%0,%1,%2,%3}, {%4,%5,%6,%7}, {%8,%9}, {%0,%1,%2,%3};"
        : "+f"(c[0]), "+f"(c[1]), "+f"(c[2]), "+f"(c[3])
        : "r"(a[0]), "r"(a[1]), "r"(a[2]), "r"(a[3]), "r"(b0), "r"(b1));
}

__device__ __forceinline__ float2 h2f2(unsigned bits) {
    return __half22float2(*reinterpret_cast<__half2*>(&bits));
}

__device__ __forceinline__ unsigned pack_h2(float a, float b) {
    __half2 h;
    h.x = __float2half_rn(a);
    h.y = __float2half_rn(b);
    return *reinterpret_cast<unsigned*>(&h);
}

// ---------------- preprocessing kernels -----------------------------------
__global__ void zero_cnt_kernel() {
    int i = blockIdx.x * blockDim.x + threadIdx.x;
    if (i < N_NODES) g_cnt[i] = 0;
}

__global__ void count_kernel(const int* __restrict__ dst) {
    int i = blockIdx.x * blockDim.x + threadIdx.x;
    if (i < N_EDGES) atomicAdd(&g_cnt[dst[i]], 1);
}

__global__ __launch_bounds__(1024)
void scan1_kernel() {
    __shared__ int sh[1024];
    int b = blockIdx.x, t = threadIdx.x;
    int idx = b * 4096 + t * 4;
    int s = 0;
    if (idx + 3 < N_NODES) {
        int4 v = *(const int4*)&g_cnt[idx];
        s = v.x + v.y + v.z + v.w;
    } else {
        for (int j = 0; j < 4; j++) if (idx + j < N_NODES) s += g_cnt[idx + j];
    }
    sh[t] = s;
    __syncthreads();
    for (int off = 512; off > 0; off >>= 1) {
        if (t < off) sh[t] += sh[t + off];
        __syncthreads();
    }
    if (t == 0) g_bsum[b] = sh[0];
}

__global__ void scan2_kernel(int nblk) {
    if (threadIdx.x == 0) {
        int acc = 0;
        for (int i = 0; i < nblk; i++) { g_boff[i] = acc; acc += g_bsum[i]; }
        g_off[N_NODES] = acc;
    }
}

// scan3 also computes dinv/selfn
__global__ __launch_bounds__(1024)
void scan3_kernel() {
    __shared__ int sh[1024];
    int b = blockIdx.x, t = threadIdx.x;
    int idx = b * 4096 + t * 4;
    int c0 = 0, c1 = 0, c2 = 0, c3 = 0;
    if (idx + 3 < N_NODES) {
        int4 v = *(const int4*)&g_cnt[idx];
        c0 = v.x; c1 = v.y; c2 = v.z; c3 = v.w;
    } else {
        if (idx + 0 < N_NODES) c0 = g_cnt[idx + 0];
        if (idx + 1 < N_NODES) c1 = g_cnt[idx + 1];
        if (idx + 2 < N_NODES) c2 = g_cnt[idx + 2];
        if (idx + 3 < N_NODES) c3 = g_cnt[idx + 3];
    }
    int s = c0 + c1 + c2 + c3;
    sh[t] = s;
    __syncthreads();
    for (int off = 1; off < 1024; off <<= 1) {
        int v = (t >= off) ? sh[t - off] : 0;
        __syncthreads();
        sh[t] += v;
        __syncthreads();
    }
    int excl = g_boff[b] + sh[t] - s;
    int4 ov = make_int4(excl, excl + c0, excl + c0 + c1, excl + c0 + c1 + c2);
    int cv[4] = {c0, c1, c2, c3};
    if (idx + 3 < N_NODES) {
        *(int4*)&g_off[idx] = ov;
        *(int4*)&g_cur[idx] = ov;
    } else {
        int o[4] = {ov.x, ov.y, ov.z, ov.w};
        for (int j = 0; j < 4; j++)
            if (idx + j < N_NODES) { g_off[idx + j] = o[j]; g_cur[idx + j] = o[j]; }
    }
    #pragma unroll
    for (int j = 0; j < 4; j++) {
        if (idx + j < N_NODES) {
            float di = rsqrtf((float)cv[j] + 1.0f);
            g_dinv[idx + j]  = di;
            g_selfn[idx + j] = di * di;
        }
    }
}

__global__ void fill_kernel(const int* __restrict__ src, const int* __restrict__ dst) {
    int i = blockIdx.x * blockDim.x + threadIdx.x;
    if (i < N_EDGES) {
        int s = src[i], d = dst[i];
        int pos = atomicAdd(&g_cur[d], 1);
        g_edge[pos] = make_int2(s, __float_as_int(g_dinv[s] * g_dinv[d]));
    }
}

// ---------------- operand packing ------------------------------------------
__global__ void convert_x_kernel(const float* __restrict__ x) {
    size_t i = ((size_t)blockIdx.x * blockDim.x + threadIdx.x) * 4;
    if (i >= (size_t)N_NODES * N_FEAT) return;
    float4 v = *(const float4*)(x + i);
    *(uint2*)&g_xh[i] = make_uint2(pack_h2(v.x, v.y), pack_h2(v.z, v.w));
}

__global__ void pack_w_kernel(const float* __restrict__ gcW0,
                              const float* __restrict__ linW0,
                              const float* __restrict__ convsW,
                              const float* __restrict__ linsW,
                              const float* __restrict__ outW) {
    int i = blockIdx.x * blockDim.x + threadIdx.x;
    if (i < 4 * 512 * 512) {
        int l = i >> 18, rem = i & 262143, n = rem >> 9, k = rem & 511;
        int Kl = l ? N_HID : N_FEAT;
        if (k >= Kl) return;
        const float* W;
        if (l == 0) W = (n < 256) ? gcW0 : linW0;
        else        W = ((n < 256) ? convsW : linsW) + (l - 1) * N_HID * N_HID;
        g_B[i] = __float2half_rn(W[k * N_HID + (n & 255)]);
    } else {
        int j = i - 4 * 512 * 512;
        if (j >= 64 * JK_DIM) return;
        int n = j >> 10, k = j & 1023;
        g_Woh[j] = __float2half_rn((n < N_CLASS) ? outW[k * N_CLASS + n] : 0.f);
    }
}

// ---------------- fp16 GEMM: C[M,512] = A[M,K] @ B[K,512], K-chunk 64 ------
#define SM_ARR 18432
#define SM_BUF 36864

__global__ __launch_bounds__(256)
void gemm_f16_kernel(const __half* __restrict__ Ax,
                     const __half* __restrict__ Bw,
                     __half* __restrict__ Chw, __half* __restrict__ Clin,
                     int M, int K, int lda)
{
    extern __shared__ char smem[];
    const unsigned sbase = su32(smem);
    int tid  = threadIdx.x;
    int lane = tid & 31;
    int wid  = tid >> 5;
    int row0 = blockIdx.y * 128;
    int col0 = blockIdx.x * 128;
    int warpM = (wid >> 2) * 64;
    int warpN = (wid & 3) * 32;

    float acc[4][4][4];
    #pragma unroll
    for (int a = 0; a < 4; a++)
        #pragma unroll
        for (int b = 0; b < 4; b++)
            #pragma unroll
            for (int c = 0; c < 4; c++) acc[a][b][c] = 0.f;

    auto stage = [&](int buf, int k0) {
        #pragma unroll
        for (int t = 0; t < 8; t++) {
            int i = tid + t * 256;
            int arr = i >> 10, rem = i & 1023, r = rem >> 3, c = rem & 7;
            unsigned dst = sbase + buf * SM_BUF + arr * SM_ARR + r * 144 + c * 16;
            const __half* src;
            unsigned sz = 16;
            if (arr == 0) {
                int gr = row0 + r;
                if (gr >= M) { gr = M - 1; sz = 0; }
                src = Ax + (size_t)gr * lda + k0 + c * 8;
            } else {
                src = Bw + (size_t)(col0 + r) * 512 + k0 + c * 8;
            }
            cp16(dst, src, sz);
        }
    };

    stage(0, 0);
    CP_COMMIT;

    const int nch = K >> 6;
    for (int ch = 0; ch < nch; ch++) {
        CP_WAIT0;
        __syncthreads();
        if (ch + 1 < nch) {
            stage((ch + 1) & 1, (ch + 1) << 6);
            CP_COMMIT;
        }

        unsigned abase = sbase + (ch & 1) * SM_BUF;
        unsigned bbase = abase + SM_ARR;
        int lrow = lane & 15;
        int lk16 = (lane >> 4) * 16;

        #pragma unroll
        for (int ks = 0; ks < 4; ks++) {
            unsigned aa[4][4];
            #pragma unroll
            for (int mt = 0; mt < 4; mt++) {
                unsigned adr = abase + (warpM + mt * 16 + lrow) * 144 + ks * 32 + lk16;
                LDSM4(aa[mt], adr);
            }
            unsigned bb[2][4];
            #pragma unroll
            for (int g = 0; g < 2; g++) {
                unsigned adr = bbase + (warpN + g * 16 + lrow) * 144 + ks * 32 + lk16;
                LDSM4(bb[g], adr);
            }
            #pragma unroll
            for (int mt = 0; mt < 4; mt++)
                #pragma unroll
                for (int nt = 0; nt < 4; nt++) {
                    int g = nt >> 1, o = nt & 1;
                    mma_f16(acc[mt][nt], aa[mt], bb[g][o], bb[g][2 + o]);
                }
        }
    }

    __half* Cg = (col0 < 256) ? Chw : Clin;
    int cb = (col0 < 256) ? col0 : (col0 - 256);
    #pragma unroll
    for (int mt = 0; mt < 4; mt++)
        #pragma unroll
        for (int nt = 0; nt < 4; nt++) {
            int r = row0 + warpM + mt * 16 + (lane >> 2);
            int c = cb + warpN + nt * 8 + (lane & 3) * 2;
            if (r < M)
                *(unsigned*)&Cg[(size_t)r * N_HID + c] =
                    pack_h2(acc[mt][nt][0], acc[mt][nt][1]);
            if (r + 8 < M)
                *(unsigned*)&Cg[(size_t)(r + 8) * N_HID + c] =
                    pack_h2(acc[mt][nt][2], acc[mt][nt][3]);
        }
}

// ---------------- fused GCN aggregation epilogue ---------------------------
__global__ __launch_bounds__(32)
void agg_kernel(const __half* __restrict__ hw, const __half* __restrict__ lin,
                const float* __restrict__ gcb, const float* __restrict__ linb,
                int slot)
{
    int n  = blockIdx.x;
    int f8 = threadIdx.x * 8;
    int beg = g_off[n], end = g_off[n + 1];

    float acc[8];
    #pragma unroll
    for (int j = 0; j < 8; j++) acc[j] = 0.f;

    int e = beg;
    for (; e + 3 < end; e += 4) {
        int2 p0 = g_edge[e],     p1 = g_edge[e + 1];
        int2 p2 = g_edge[e + 2], p3 = g_edge[e + 3];
        uint4 v0 = *(const uint4*)&hw[(size_t)p0.x * N_HID + f8];
        uint4 v1 = *(const uint4*)&hw[(size_t)p1.x * N_HID + f8];
        uint4 v2 = *(const uint4*)&hw[(size_t)p2.x * N_HID + f8];
        uint4 v3 = *(const uint4*)&hw[(size_t)p3.x * N_HID + f8];
        float c0 = __int_as_float(p0.y), c1 = __int_as_float(p1.y);
        float c2 = __int_as_float(p2.y), c3 = __int_as_float(p3.y);
        const unsigned* w0 = &v0.x; const unsigned* w1 = &v1.x;
        const unsigned* w2 = &v2.x; const unsigned* w3 = &v3.x;
        #pragma unroll
        for (int j = 0; j < 4; j++) {
            float2 f0 = h2f2(w0[j]), f1 = h2f2(w1[j]);
            float2 f2 = h2f2(w2[j]), f3 = h2f2(w3[j]);
            acc[2*j]   += c0 * f0.x + c1 * f1.x + c2 * f2.x + c3 * f3.x;
            acc[2*j+1] += c0 * f0.y + c1 * f1.y + c2 * f2.y + c3 * f3.y;
        }
    }
    for (; e < end; e++) {
        int2 p = g_edge[e];
        uint4 v = *(const uint4*)&hw[(size_t)p.x * N_HID + f8];
        float c = __int_as_float(p.y);
        const unsigned* w = &v.x;
        #pragma unroll
        for (int j = 0; j < 4; j++) {
            float2 f = h2f2(w[j]);
            acc[2*j]   += c * f.x;
            acc[2*j+1] += c * f.y;
        }
    }

    float sn = g_selfn[n];
    uint4 vs = *(const uint4*)&hw [(size_t)n * N_HID + f8];
    uint4 vl = *(const uint4*)&lin[(size_t)n * N_HID + f8];
    float4 bg0 = *(const float4*)&gcb[f8];
    float4 bg1 = *(const float4*)&gcb[f8 + 4];
    float4 bl0 = *(const float4*)&linb[f8];
    float4 bl1 = *(const float4*)&linb[f8 + 4];
    float bgv[8] = {bg0.x, bg0.y, bg0.z, bg0.w, bg1.x, bg1.y, bg1.z, bg1.w};
    float blv[8] = {bl0.x, bl0.y, bl0.z, bl0.w, bl1.x, bl1.y, bl1.z, bl1.w};

    const unsigned* ws = &vs.x;
    const unsigned* wl = &vl.x;
    unsigned hh[4];
    #pragma unroll
    for (int j = 0; j < 4; j++) {
        float2 fs = h2f2(ws[j]);
        float2 fl = h2f2(wl[j]);
        float r0 = fmaxf(acc[2*j]   + sn * fs.x + bgv[2*j]   + fl.x + blv[2*j],   0.f);
        float r1 = fmaxf(acc[2*j+1] + sn * fs.y + bgv[2*j+1] + fl.y + blv[2*j+1], 0.f);
        hh[j] = pack_h2(r0, r1);
    }
    size_t o = (size_t)n * JK_DIM + slot * N_HID + f8;
    *(uint4*)&g_jkh[o] = make_uint4(hh[0], hh[1], hh[2], hh[3]);
}

// ---------------- output GEMM (single-term fp16) ---------------------------
#define OSM_A  10240
#define OSM_B  5120
#define OSM_BUF (OSM_A + OSM_B)   // 15360

__global__ __launch_bounds__(256)
void out_mma_kernel(const float* __restrict__ bias, float* __restrict__ out)
{
    extern __shared__ char smem[];
    const unsigned sbase = su32(smem);
    int tid  = threadIdx.x;
    int lane = tid & 31;
    int wid  = tid >> 5;
    int row0 = blockIdx.x * 128;

    float acc[5][4];
    #pragma unroll
    for (int a = 0; a < 5; a++)
        #pragma unroll
        for (int c = 0; c < 4; c++) acc[a][c] = 0.f;

    auto stage = [&](int buf, int k0) {
        #pragma unroll
        for (int t = 0; t < 3; t++) {
            int i = tid + t * 256;
            unsigned dst; const __half* src; unsigned sz = 16;
            if (i < 512) {
                int r = i >> 2, c = i & 3;
                int gr = row0 + r;
                if (gr >= N_NODES) { gr = N_NODES - 1; sz = 0; }
                src = g_jkh + (size_t)gr * JK_DIM + k0 + c * 8;
                dst = sbase + buf * OSM_BUF + r * 80 + c * 16;
            } else {
                int j = i - 512;
                int r = j >> 2, c = j & 3;
                src = g_Woh + (size_t)r * JK_DIM + k0 + c * 8;
                dst = sbase + buf * OSM_BUF + OSM_A + r * 80 + c * 16;
            }
            cp16(dst, src, sz);
        }
    };

    stage(0, 0);
    CP_COMMIT;

    const int nch = JK_DIM / 32;
    for (int ch = 0; ch < nch; ch++) {
        CP_WAIT0;
        __syncthreads();
        if (ch + 1 < nch) {
            stage((ch + 1) & 1, (ch + 1) * 32);
            CP_COMMIT;
        }

        unsigned abase = sbase + (ch & 1) * OSM_BUF;
        unsigned bbase = abase + OSM_A;
        int lrow = lane & 15;
        int lk16 = (lane >> 4) * 16;

        #pragma unroll
        for (int ks = 0; ks < 2; ks++) {
            unsigned ah[4];
            unsigned adr = abase + (wid * 16 + lrow) * 80 + ks * 32 + lk16;
            LDSM4(ah, adr);
            unsigned bh[3][4];
            #pragma unroll
            for (int g = 0; g < 3; g++) {
                unsigned badr = bbase + (g * 16 + lrow) * 80 + ks * 32 + lk16;
                LDSM4(bh[g], badr);
            }
            #pragma unroll
            for (int nt = 0; nt < 5; nt++) {
                int g = nt >> 1, o = nt & 1;
                mma_f16(acc[nt], ah, bh[g][o], bh[g][2 + o]);
            }
        }
    }

    #pragma unroll
    for (int nt = 0; nt < 5; nt++) {
        int c = nt * 8 + (lane & 3) * 2;
        float2 bv = make_float2(bias[c], bias[c + 1]);
        int r = row0 + wid * 16 + (lane >> 2);
        if (r < N_NODES)
            *(float2*)&out[(size_t)r * N_CLASS + c] =
                make_float2(acc[nt][0] + bv.x, acc[nt][1] + bv.y);
        if (r + 8 < N_NODES)
            *(float2*)&out[(size_t)(r + 8) * N_CLASS + c] =
                make_float2(acc[nt][2] + bv.x, acc[nt][3] + bv.y);
    }
}

// ---------------- launch ---------------------------------------------------
extern "C" void kernel_launch(void* const* d_in, const int* in_sizes, int n_in,
                              void* d_out, int out_size)
{
    const float* x        = (const float*)d_in[0];
    const int*   edge     = (const int*)  d_in[1];
    const float* in_gc_W  = (const float*)d_in[2];
    const float* in_gc_b  = (const float*)d_in[3];
    const float* in_lin_W = (const float*)d_in[4];
    const float* in_lin_b = (const float*)d_in[5];
    const float* convs_W  = (const float*)d_in[6];
    const float* convs_b  = (const float*)d_in[7];
    const float* lins_W   = (const float*)d_in[8];
    const float* lins_b   = (const float*)d_in[9];
    const float* out_W    = (const float*)d_in[10];
    const float* out_b    = (const float*)d_in[11];
    float*       out      = (float*)d_out;

    const int* src = edge;
    const int* dst = edge + N_EDGES;

    __half *p_hw, *p_lin, *p_xh, *p_jkh, *p_B;
    cudaGetSymbolAddress((void**)&p_hw,  g_hw);
    cudaGetSymbolAddress((void**)&p_lin, g_lin);
    cudaGetSymbolAddress((void**)&p_xh,  g_xh);
    cudaGetSymbolAddress((void**)&p_jkh, g_jkh);
    cudaGetSymbolAddress((void**)&p_B,   g_B);

    cudaFuncSetAttribute(gemm_f16_kernel,
                         cudaFuncAttributeMaxDynamicSharedMemorySize, 2 * SM_BUF);
    cudaFuncSetAttribute(out_mma_kernel,
                         cudaFuncAttributeMaxDynamicSharedMemorySize, 2 * OSM_BUF);

    // side stream + fork/join events for capture-parallel preprocessing
    cudaStream_t s2;
    cudaStreamCreateWithFlags(&s2, cudaStreamNonBlocking);
    cudaEvent_t e_fork, e_join;
    cudaEventCreateWithFlags(&e_fork, cudaEventDisableTiming);
    cudaEventCreateWithFlags(&e_join, cudaEventDisableTiming);

    dim3 ggrid(4, (N_NODES + 127) / 128);

    // fork: CSR-build branch on s2, operand packing + gemm0 on main stream
    cudaEventRecord(e_fork, 0);
    cudaStreamWaitEvent(s2, e_fork, 0);

    // s2 branch: zero -> count -> scan -> fill (independent of gemm0)
    zero_cnt_kernel<<<(N_NODES + 255) / 256, 256, 0, s2>>>();
    count_kernel<<<(N_EDGES + 255) / 256, 256, 0, s2>>>(dst);
    scan1_kernel<<<13, 1024, 0, s2>>>();
    scan2_kernel<<<1, 32, 0, s2>>>(13);
    scan3_kernel<<<13, 1024, 0, s2>>>();
    fill_kernel<<<(N_EDGES + 255) / 256, 256, 0, s2>>>(src, dst);
    cudaEventRecord(e_join, s2);

    // main stream: pack + layer-0 GEMM (overlaps the s2 branch)
    convert_x_kernel<<<(N_NODES * N_FEAT / 4 + 255) / 256, 256>>>(x);
    pack_w_kernel<<<(4 * 512 * 512 + 64 * JK_DIM + 255) / 256, 256>>>(
        in_gc_W, in_lin_W, convs_W, lins_W, out_W);
    gemm_f16_kernel<<<ggrid, 256, 2 * SM_BUF>>>(
        p_xh, p_B, p_hw, p_lin, N_NODES, N_FEAT, N_FEAT);

    // join: agg needs both gemm0 and the CSR
    cudaStreamWaitEvent(0, e_join, 0);
    agg_kernel<<<N_NODES, 32>>>(p_hw, p_lin, in_gc_b, in_lin_b, 0);

    for (int i = 0; i < N_LAYER - 1; i++) {
        gemm_f16_kernel<<<ggrid, 256, 2 * SM_BUF>>>(
            p_jkh + i * N_HID, p_B + (size_t)(i + 1) * 512 * 512,
            p_hw, p_lin, N_NODES, N_HID, JK_DIM);
        agg_kernel<<<N_NODES, 32>>>(p_hw, p_lin,
                                    convs_b + i * N_HID, lins_b + i * N_HID,
                                    i + 1);
    }

    out_mma_kernel<<<(N_NODES + 127) / 128, 256, 2 * OSM_BUF>>>(out_b, out);
}

// round 15
// speedup vs baseline: 1.6891x; 1.0747x over previous
#include <cuda_runtime.h>
#include <cuda_fp16.h>

#define N_NODES 50000
#define N_EDGES 800000
#define N_FEAT  512
#define N_HID   256
#define N_LAYER 4
#define N_CLASS 40
#define JK_DIM  (N_HID * N_LAYER)   // 1024
#define NSCAN_BLK 13

// ---------------- scratch (device globals; no allocation allowed) ----------
__device__ int   g_cnt[N_NODES];
__device__ int   g_off[N_NODES + 1];
__device__ int   g_cur[N_NODES];
__device__ int   g_bsum[16];
__device__ __align__(16) int2 g_edge[N_EDGES];      // {src, coef bits}
__device__ float g_dinv[N_NODES];
__device__ float g_selfn[N_NODES];
__device__ __align__(256) __half g_hw [N_NODES * N_HID];
__device__ __align__(256) __half g_lin[N_NODES * N_HID];
__device__ __align__(256) __half g_jkh[(size_t)N_NODES * JK_DIM];
__device__ __align__(256) __half g_xh[(size_t)N_NODES * N_FEAT];
__device__ __align__(256) __half g_B[4 * 512 * 512];
__device__ __align__(256) __half g_Woh[64 * JK_DIM];
__device__ __align__(256) float  g_outp[(size_t)50048 * 64];   // partial out acc

// ---------------- helpers ---------------------------------------------------
__device__ __forceinline__ unsigned su32(const void* p) {
    unsigned a;
    asm("{ .reg .u64 t; cvta.to.shared.u64 t, %1; cvt.u32.u64 %0, t; }"
        : "=r"(a) : "l"(p));
    return a;
}

__device__ __forceinline__ void cp16(unsigned d, const void* s, unsigned sz) {
    asm volatile("cp.async.cg.shared.global [%0], [%1], 16, %2;"
                 :: "r"(d), "l"(s), "r"(sz) : "memory");
}
#define CP_COMMIT asm volatile("cp.async.commit_group;" ::: "memory")
#define CP_WAIT0  asm volatile("cp.async.wait_group 0;" ::: "memory")

#define LDSM4(r, a) \
    asm volatile("ldmatrix.sync.aligned.m8n8.x4.shared.b16 {%0,%1,%2,%3}, [%4];" \
        : "=r"((r)[0]), "=r"((r)[1]), "=r"((r)[2]), "=r"((r)[3]) : "r"(a))

__device__ __forceinline__ void mma_f16(float* c, const unsigned* a,
                                        unsigned b0, unsigned b1) {
    asm volatile("mma.sync.aligned.m16n8k16.row.col.f32.f16.f16.f32 "
        "{%0,%1,%2,%3}, {%4,%5,%6,%7}, {%8,%9}, {%0,%1,%2,%3};"
        : "+f"(c[0]), "+f"(c[1]), "+f"(c[2]), "+f"(c[3])
        : "r"(a[0]), "r"(a[1]), "r"(a[2]), "r"(a[3]), "r"(b0), "r"(b1));
}

__device__ __forceinline__ float2 h2f2(unsigned bits) {
    return __half22float2(*reinterpret_cast<__half2*>(&bits));
}

__device__ __forceinline__ unsigned pack_h2(float a, float b) {
    __half2 h;
    h.x = __float2half_rn(a);
    h.y = __float2half_rn(b);
    return *reinterpret_cast<unsigned*>(&h);
}

// ---------------- preprocessing kernels -----------------------------------
__global__ void zero_cnt_kernel() {
    int i = blockIdx.x * blockDim.x + threadIdx.x;
    if (i < N_NODES) g_cnt[i] = 0;
}

__global__ void count_kernel(const int* __restrict__ dst) {
    int i = blockIdx.x * blockDim.x + threadIdx.x;
    if (i < N_EDGES) atomicAdd(&g_cnt[dst[i]], 1);
}

__global__ __launch_bounds__(1024)
void scan1_kernel() {
    __shared__ int sh[1024];
    int b = blockIdx.x, t = threadIdx.x;
    int idx = b * 4096 + t * 4;
    int s = 0;
    if (idx + 3 < N_NODES) {
        int4 v = *(const int4*)&g_cnt[idx];
        s = v.x + v.y + v.z + v.w;
    } else {
        for (int j = 0; j < 4; j++) if (idx + j < N_NODES) s += g_cnt[idx + j];
    }
    sh[t] = s;
    __syncthreads();
    for (int off = 512; off > 0; off >>= 1) {
        if (t < off) sh[t] += sh[t + off];
        __syncthreads();
    }
    if (t == 0) g_bsum[b] = sh[0];
}

// scan3: per-block prefix of g_bsum computed locally (scan2 folded in);
// also computes dinv/selfn
__global__ __launch_bounds__(1024)
void scan3_kernel() {
    __shared__ int sh[1024];
    int b = blockIdx.x, t = threadIdx.x;
    int boff = 0, tot = 0;
    #pragma unroll
    for (int i = 0; i < NSCAN_BLK; i++) {
        int v = g_bsum[i];
        if (i < b) boff += v;
        tot += v;
    }
    int idx = b * 4096 + t * 4;
    int c0 = 0, c1 = 0, c2 = 0, c3 = 0;
    if (idx + 3 < N_NODES) {
        int4 v = *(const int4*)&g_cnt[idx];
        c0 = v.x; c1 = v.y; c2 = v.z; c3 = v.w;
    } else {
        if (idx + 0 < N_NODES) c0 = g_cnt[idx + 0];
        if (idx + 1 < N_NODES) c1 = g_cnt[idx + 1];
        if (idx + 2 < N_NODES) c2 = g_cnt[idx + 2];
        if (idx + 3 < N_NODES) c3 = g_cnt[idx + 3];
    }
    int s = c0 + c1 + c2 + c3;
    sh[t] = s;
    __syncthreads();
    for (int off = 1; off < 1024; off <<= 1) {
        int v = (t >= off) ? sh[t - off] : 0;
        __syncthreads();
        sh[t] += v;
        __syncthreads();
    }
    int excl = boff + sh[t] - s;
    int4 ov = make_int4(excl, excl + c0, excl + c0 + c1, excl + c0 + c1 + c2);
    int cv[4] = {c0, c1, c2, c3};
    if (idx + 3 < N_NODES) {
        *(int4*)&g_off[idx] = ov;
        *(int4*)&g_cur[idx] = ov;
    } else {
        int o[4] = {ov.x, ov.y, ov.z, ov.w};
        for (int j = 0; j < 4; j++)
            if (idx + j < N_NODES) { g_off[idx + j] = o[j]; g_cur[idx + j] = o[j]; }
    }
    #pragma unroll
    for (int j = 0; j < 4; j++) {
        if (idx + j < N_NODES) {
            float di = rsqrtf((float)cv[j] + 1.0f);
            g_dinv[idx + j]  = di;
            g_selfn[idx + j] = di * di;
        }
    }
    if (b == NSCAN_BLK - 1 && t == 0) g_off[N_NODES] = tot;
}

__global__ void fill_kernel(const int* __restrict__ src, const int* __restrict__ dst) {
    int i = blockIdx.x * blockDim.x + threadIdx.x;
    if (i < N_EDGES) {
        int s = src[i], d = dst[i];
        int pos = atomicAdd(&g_cur[d], 1);
        g_edge[pos] = make_int2(s, __float_as_int(g_dinv[s] * g_dinv[d]));
    }
}

// ---------------- operand packing ------------------------------------------
__global__ void convert_x_kernel(const float* __restrict__ x) {
    size_t i = ((size_t)blockIdx.x * blockDim.x + threadIdx.x) * 4;
    if (i >= (size_t)N_NODES * N_FEAT) return;
    float4 v = *(const float4*)(x + i);
    *(uint2*)&g_xh[i] = make_uint2(pack_h2(v.x, v.y), pack_h2(v.z, v.w));
}

__global__ void pack_w_kernel(const float* __restrict__ gcW0,
                              const float* __restrict__ linW0,
                              const float* __restrict__ convsW,
                              const float* __restrict__ linsW,
                              const float* __restrict__ outW) {
    int i = blockIdx.x * blockDim.x + threadIdx.x;
    if (i < 4 * 512 * 512) {
        int l = i >> 18, rem = i & 262143, n = rem >> 9, k = rem & 511;
        int Kl = l ? N_HID : N_FEAT;
        if (k >= Kl) return;
        const float* W;
        if (l == 0) W = (n < 256) ? gcW0 : linW0;
        else        W = ((n < 256) ? convsW : linsW) + (l - 1) * N_HID * N_HID;
        g_B[i] = __float2half_rn(W[k * N_HID + (n & 255)]);
    } else {
        int j = i - 4 * 512 * 512;
        if (j >= 64 * JK_DIM) return;
        int n = j >> 10, k = j & 1023;
        g_Woh[j] = __float2half_rn((n < N_CLASS) ? outW[k * N_CLASS + n] : 0.f);
    }
}

// ---------------- fp16 GEMM: C[M,512] = A[M,K] @ B[K,512], K-chunk 64 ------
#define SM_ARR 18432
#define SM_BUF 36864

__global__ __launch_bounds__(256)
void gemm_f16_kernel(const __half* __restrict__ Ax,
                     const __half* __restrict__ Bw,
                     __half* __restrict__ Chw, __half* __restrict__ Clin,
                     int M, int K, int lda)
{
    extern __shared__ char smem[];
    const unsigned sbase = su32(smem);
    int tid  = threadIdx.x;
    int lane = tid & 31;
    int wid  = tid >> 5;
    int row0 = blockIdx.y * 128;
    int col0 = blockIdx.x * 128;
    int warpM = (wid >> 2) * 64;
    int warpN = (wid & 3) * 32;

    float acc[4][4][4];
    #pragma unroll
    for (int a = 0; a < 4; a++)
        #pragma unroll
        for (int b = 0; b < 4; b++)
            #pragma unroll
            for (int c = 0; c < 4; c++) acc[a][b][c] = 0.f;

    auto stage = [&](int buf, int k0) {
        #pragma unroll
        for (int t = 0; t < 8; t++) {
            int i = tid + t * 256;
            int arr = i >> 10, rem = i & 1023, r = rem >> 3, c = rem & 7;
            unsigned dst = sbase + buf * SM_BUF + arr * SM_ARR + r * 144 + c * 16;
            const __half* src;
            unsigned sz = 16;
            if (arr == 0) {
                int gr = row0 + r;
                if (gr >= M) { gr = M - 1; sz = 0; }
                src = Ax + (size_t)gr * lda + k0 + c * 8;
            } else {
                src = Bw + (size_t)(col0 + r) * 512 + k0 + c * 8;
            }
            cp16(dst, src, sz);
        }
    };

    stage(0, 0);
    CP_COMMIT;

    const int nch = K >> 6;
    for (int ch = 0; ch < nch; ch++) {
        CP_WAIT0;
        __syncthreads();
        if (ch + 1 < nch) {
            stage((ch + 1) & 1, (ch + 1) << 6);
            CP_COMMIT;
        }

        unsigned abase = sbase + (ch & 1) * SM_BUF;
        unsigned bbase = abase + SM_ARR;
        int lrow = lane & 15;
        int lk16 = (lane >> 4) * 16;

        #pragma unroll
        for (int ks = 0; ks < 4; ks++) {
            unsigned aa[4][4];
            #pragma unroll
            for (int mt = 0; mt < 4; mt++) {
                unsigned adr = abase + (warpM + mt * 16 + lrow) * 144 + ks * 32 + lk16;
                LDSM4(aa[mt], adr);
            }
            unsigned bb[2][4];
            #pragma unroll
            for (int g = 0; g < 2; g++) {
                unsigned adr = bbase + (warpN + g * 16 + lrow) * 144 + ks * 32 + lk16;
                LDSM4(bb[g], adr);
            }
            #pragma unroll
            for (int mt = 0; mt < 4; mt++)
                #pragma unroll
                for (int nt = 0; nt < 4; nt++) {
                    int g = nt >> 1, o = nt & 1;
                    mma_f16(acc[mt][nt], aa[mt], bb[g][o], bb[g][2 + o]);
                }
        }
    }

    __half* Cg = (col0 < 256) ? Chw : Clin;
    int cb = (col0 < 256) ? col0 : (col0 - 256);
    #pragma unroll
    for (int mt = 0; mt < 4; mt++)
        #pragma unroll
        for (int nt = 0; nt < 4; nt++) {
            int r = row0 + warpM + mt * 16 + (lane >> 2);
            int c = cb + warpN + nt * 8 + (lane & 3) * 2;
            if (r < M)
                *(unsigned*)&Cg[(size_t)r * N_HID + c] =
                    pack_h2(acc[mt][nt][0], acc[mt][nt][1]);
            if (r + 8 < M)
                *(unsigned*)&Cg[(size_t)(r + 8) * N_HID + c] =
                    pack_h2(acc[mt][nt][2], acc[mt][nt][3]);
        }
}

// ---------------- fused GCN aggregation: 2 nodes per 64-thread block -------
__global__ __launch_bounds__(64)
void agg_kernel(const __half* __restrict__ hw, const __half* __restrict__ lin,
                const float* __restrict__ gcb, const float* __restrict__ linb,
                int slot)
{
    int warp = threadIdx.x >> 5;
    int lane = threadIdx.x & 31;
    int n  = blockIdx.x * 2 + warp;
    if (n >= N_NODES) return;
    int f8 = lane * 8;
    int beg = g_off[n], end = g_off[n + 1];

    float acc[8];
    #pragma unroll
    for (int j = 0; j < 8; j++) acc[j] = 0.f;

    int e = beg;
    for (; e + 3 < end; e += 4) {
        int2 p0 = g_edge[e],     p1 = g_edge[e + 1];
        int2 p2 = g_edge[e + 2], p3 = g_edge[e + 3];
        uint4 v0 = *(const uint4*)&hw[(size_t)p0.x * N_HID + f8];
        uint4 v1 = *(const uint4*)&hw[(size_t)p1.x * N_HID + f8];
        uint4 v2 = *(const uint4*)&hw[(size_t)p2.x * N_HID + f8];
        uint4 v3 = *(const uint4*)&hw[(size_t)p3.x * N_HID + f8];
        float c0 = __int_as_float(p0.y), c1 = __int_as_float(p1.y);
        float c2 = __int_as_float(p2.y), c3 = __int_as_float(p3.y);
        const unsigned* w0 = &v0.x; const unsigned* w1 = &v1.x;
        const unsigned* w2 = &v2.x; const unsigned* w3 = &v3.x;
        #pragma unroll
        for (int j = 0; j < 4; j++) {
            float2 f0 = h2f2(w0[j]), f1 = h2f2(w1[j]);
            float2 f2 = h2f2(w2[j]), f3 = h2f2(w3[j]);
            acc[2*j]   += c0 * f0.x + c1 * f1.x + c2 * f2.x + c3 * f3.x;
            acc[2*j+1] += c0 * f0.y + c1 * f1.y + c2 * f2.y + c3 * f3.y;
        }
    }
    for (; e < end; e++) {
        int2 p = g_edge[e];
        uint4 v = *(const uint4*)&hw[(size_t)p.x * N_HID + f8];
        float c = __int_as_float(p.y);
        const unsigned* w = &v.x;
        #pragma unroll
        for (int j = 0; j < 4; j++) {
            float2 f = h2f2(w[j]);
            acc[2*j]   += c * f.x;
            acc[2*j+1] += c * f.y;
        }
    }

    float sn = g_selfn[n];
    uint4 vs = *(const uint4*)&hw [(size_t)n * N_HID + f8];
    uint4 vl = *(const uint4*)&lin[(size_t)n * N_HID + f8];
    float4 bg0 = *(const float4*)&gcb[f8];
    float4 bg1 = *(const float4*)&gcb[f8 + 4];
    float4 bl0 = *(const float4*)&linb[f8];
    float4 bl1 = *(const float4*)&linb[f8 + 4];
    float bgv[8] = {bg0.x, bg0.y, bg0.z, bg0.w, bg1.x, bg1.y, bg1.z, bg1.w};
    float blv[8] = {bl0.x, bl0.y, bl0.z, bl0.w, bl1.x, bl1.y, bl1.z, bl1.w};

    const unsigned* ws = &vs.x;
    const unsigned* wl = &vl.x;
    unsigned hh[4];
    #pragma unroll
    for (int j = 0; j < 4; j++) {
        float2 fs = h2f2(ws[j]);
        float2 fl = h2f2(wl[j]);
        float r0 = fmaxf(acc[2*j]   + sn * fs.x + bgv[2*j]   + fl.x + blv[2*j],   0.f);
        float r1 = fmaxf(acc[2*j+1] + sn * fs.y + bgv[2*j+1] + fl.y + blv[2*j+1], 0.f);
        hh[j] = pack_h2(r0, r1);
    }
    size_t o = (size_t)n * JK_DIM + slot * N_HID + f8;
    *(uint4*)&g_jkh[o] = make_uint4(hh[0], hh[1], hh[2], hh[3]);
}

// ---------------- output GEMM, split into partial + final ------------------
#define OSM_A  10240
#define OSM_B  5120
#define OSM_BUF (OSM_A + OSM_B)   // 15360

// shared mainloop: processes K range [kbeg, kbeg + nch*32)
template<int NCH, bool FINAL>
__device__ __forceinline__ void out_mma_body(const float* bias, float* out,
                                             int kbeg)
{
    extern __shared__ char smem[];
    const unsigned sbase = su32(smem);
    int tid  = threadIdx.x;
    int lane = tid & 31;
    int wid  = tid >> 5;
    int row0 = blockIdx.x * 128;

    float acc[5][4];
    #pragma unroll
    for (int a = 0; a < 5; a++)
        #pragma unroll
        for (int c = 0; c < 4; c++) acc[a][c] = 0.f;

    auto stage = [&](int buf, int k0) {
        #pragma unroll
        for (int t = 0; t < 3; t++) {
            int i = tid + t * 256;
            unsigned dst; const __half* src; unsigned sz = 16;
            if (i < 512) {
                int r = i >> 2, c = i & 3;
                int gr = row0 + r;
                if (gr >= N_NODES) { gr = N_NODES - 1; sz = 0; }
                src = g_jkh + (size_t)gr * JK_DIM + k0 + c * 8;
                dst = sbase + buf * OSM_BUF + r * 80 + c * 16;
            } else {
                int j = i - 512;
                int r = j >> 2, c = j & 3;
                src = g_Woh + (size_t)r * JK_DIM + k0 + c * 8;
                dst = sbase + buf * OSM_BUF + OSM_A + r * 80 + c * 16;
            }
            cp16(dst, src, sz);
        }
    };

    stage(0, kbeg);
    CP_COMMIT;

    for (int ch = 0; ch < NCH; ch++) {
        CP_WAIT0;
        __syncthreads();
        if (ch + 1 < NCH) {
            stage((ch + 1) & 1, kbeg + (ch + 1) * 32);
            CP_COMMIT;
        }

        unsigned abase = sbase + (ch & 1) * OSM_BUF;
        unsigned bbase = abase + OSM_A;
        int lrow = lane & 15;
        int lk16 = (lane >> 4) * 16;

        #pragma unroll
        for (int ks = 0; ks < 2; ks++) {
            unsigned ah[4];
            unsigned adr = abase + (wid * 16 + lrow) * 80 + ks * 32 + lk16;
            LDSM4(ah, adr);
            unsigned bh[3][4];
            #pragma unroll
            for (int g = 0; g < 3; g++) {
                unsigned badr = bbase + (g * 16 + lrow) * 80 + ks * 32 + lk16;
                LDSM4(bh[g], badr);
            }
            #pragma unroll
            for (int nt = 0; nt < 5; nt++) {
                int g = nt >> 1, o = nt & 1;
                mma_f16(acc[nt], ah, bh[g][o], bh[g][2 + o]);
            }
        }
    }

    #pragma unroll
    for (int nt = 0; nt < 5; nt++) {
        int c = nt * 8 + (lane & 3) * 2;
        int r = row0 + wid * 16 + (lane >> 2);
        if (FINAL) {
            float2 bv = make_float2(bias[c], bias[c + 1]);
            if (r < N_NODES) {
                float2 pv = *(float2*)&g_outp[(size_t)r * 64 + c];
                *(float2*)&out[(size_t)r * N_CLASS + c] =
                    make_float2(acc[nt][0] + pv.x + bv.x,
                                acc[nt][1] + pv.y + bv.y);
            }
            if (r + 8 < N_NODES) {
                float2 pv = *(float2*)&g_outp[(size_t)(r + 8) * 64 + c];
                *(float2*)&out[(size_t)(r + 8) * N_CLASS + c] =
                    make_float2(acc[nt][2] + pv.x + bv.x,
                                acc[nt][3] + pv.y + bv.y);
            }
        } else {
            // partial: always in-bounds rows of g_outp (padded to 50048)
            *(float2*)&g_outp[(size_t)r * 64 + c] =
                make_float2(acc[nt][0], acc[nt][1]);
            *(float2*)&g_outp[(size_t)(r + 8) * 64 + c] =
                make_float2(acc[nt][2], acc[nt][3]);
        }
    }
}

__global__ __launch_bounds__(256)
void out_partial_kernel() {
    out_mma_body<24, false>(nullptr, nullptr, 0);     // K 0..767 (slots 0-2)
}

__global__ __launch_bounds__(256)
void out_final_kernel(const float* __restrict__ bias, float* __restrict__ out) {
    out_mma_body<8, true>(bias, out, 768);            // K 768..1023 (slot 3)
}

// ---------------- launch ---------------------------------------------------
extern "C" void kernel_launch(void* const* d_in, const int* in_sizes, int n_in,
                              void* d_out, int out_size)
{
    const float* x        = (const float*)d_in[0];
    const int*   edge     = (const int*)  d_in[1];
    const float* in_gc_W  = (const float*)d_in[2];
    const float* in_gc_b  = (const float*)d_in[3];
    const float* in_lin_W = (const float*)d_in[4];
    const float* in_lin_b = (const float*)d_in[5];
    const float* convs_W  = (const float*)d_in[6];
    const float* convs_b  = (const float*)d_in[7];
    const float* lins_W   = (const float*)d_in[8];
    const float* lins_b   = (const float*)d_in[9];
    const float* out_W    = (const float*)d_in[10];
    const float* out_b    = (const float*)d_in[11];
    float*       out      = (float*)d_out;

    const int* src = edge;
    const int* dst = edge + N_EDGES;

    __half *p_hw, *p_lin, *p_xh, *p_jkh, *p_B;
    cudaGetSymbolAddress((void**)&p_hw,  g_hw);
    cudaGetSymbolAddress((void**)&p_lin, g_lin);
    cudaGetSymbolAddress((void**)&p_xh,  g_xh);
    cudaGetSymbolAddress((void**)&p_jkh, g_jkh);
    cudaGetSymbolAddress((void**)&p_B,   g_B);

    cudaFuncSetAttribute(gemm_f16_kernel,
                         cudaFuncAttributeMaxDynamicSharedMemorySize, 2 * SM_BUF);
    cudaFuncSetAttribute(out_partial_kernel,
                         cudaFuncAttributeMaxDynamicSharedMemorySize, 2 * OSM_BUF);
    cudaFuncSetAttribute(out_final_kernel,
                         cudaFuncAttributeMaxDynamicSharedMemorySize, 2 * OSM_BUF);

    cudaStream_t s2;
    cudaStreamCreateWithFlags(&s2, cudaStreamNonBlocking);
    cudaEvent_t e_fork, e_join, e_slot2, e_part;
    cudaEventCreateWithFlags(&e_fork,  cudaEventDisableTiming);
    cudaEventCreateWithFlags(&e_join,  cudaEventDisableTiming);
    cudaEventCreateWithFlags(&e_slot2, cudaEventDisableTiming);
    cudaEventCreateWithFlags(&e_part,  cudaEventDisableTiming);

    dim3 ggrid(4, (N_NODES + 127) / 128);
    int agg_grid = (N_NODES + 1) / 2;
    int out_grid = (N_NODES + 127) / 128;

    // fork: CSR-build branch on s2; packing + gemm0 on main
    cudaEventRecord(e_fork, 0);
    cudaStreamWaitEvent(s2, e_fork, 0);

    zero_cnt_kernel<<<(N_NODES + 255) / 256, 256, 0, s2>>>();
    count_kernel<<<(N_EDGES + 255) / 256, 256, 0, s2>>>(dst);
    scan1_kernel<<<NSCAN_BLK, 1024, 0, s2>>>();
    scan3_kernel<<<NSCAN_BLK, 1024, 0, s2>>>();
    fill_kernel<<<(N_EDGES + 255) / 256, 256, 0, s2>>>(src, dst);
    cudaEventRecord(e_join, s2);

    convert_x_kernel<<<(N_NODES * N_FEAT / 4 + 255) / 256, 256>>>(x);
    pack_w_kernel<<<(4 * 512 * 512 + 64 * JK_DIM + 255) / 256, 256>>>(
        in_gc_W, in_lin_W, convs_W, lins_W, out_W);
    gemm_f16_kernel<<<ggrid, 256, 2 * SM_BUF>>>(
        p_xh, p_B, p_hw, p_lin, N_NODES, N_FEAT, N_FEAT);

    cudaStreamWaitEvent(0, e_join, 0);
    agg_kernel<<<agg_grid, 64>>>(p_hw, p_lin, in_gc_b, in_lin_b, 0);

    for (int i = 0; i < N_LAYER - 1; i++) {
        gemm_f16_kernel<<<ggrid, 256, 2 * SM_BUF>>>(
            p_jkh + i * N_HID, p_B + (size_t)(i + 1) * 512 * 512,
            p_hw, p_lin, N_NODES, N_HID, JK_DIM);
        agg_kernel<<<agg_grid, 64>>>(p_hw, p_lin,
                                     convs_b + i * N_HID, lins_b + i * N_HID,
                                     i + 1);
        if (i == 1) {
            // jk slots 0-2 complete -> start partial output GEMM on s2,
            // overlapping gemm3 + agg3 on the main stream
            cudaEventRecord(e_slot2, 0);
            cudaStreamWaitEvent(s2, e_slot2, 0);
            out_partial_kernel<<<out_grid, 256, 2 * OSM_BUF, s2>>>();
            cudaEventRecord(e_part, s2);
        }
    }

    cudaStreamWaitEvent(0, e_part, 0);
    out_final_kernel<<<out_grid, 256, 2 * OSM_BUF>>>(out_b, out);
}